// round 1
// baseline (speedup 1.0000x reference)
#include <cuda_runtime.h>
#include <math.h>

#define NB 8
#define NP 1024
#define ND 64
#define GAMMA 10.0f
#define MARGIN 0.1f

// ---------------- device scratch (no allocs allowed) ----------------
__device__ float d_feat[4][NB * NP * ND];      // normalized x1..x4 (8 MB)
__device__ float d_C[NB * NP * NP];            // cost TL block (32 MB)
__device__ float d_CT[NB * NP * NP];           // transposed cost (32 MB)
__device__ float d_r[NB * NP];                 // row sums of sim
__device__ float d_c[NB * NP];                 // col sums of sim
__device__ float d_f[2][NB * NP];              // dual f ping-pong
__device__ float d_g[2][NB * NP];              // dual g ping-pong
__device__ double d_hinge;
__device__ double d_scon;

// ---------------- reset ----------------
__global__ void reset_kernel() {
    int i = blockIdx.x * blockDim.x + threadIdx.x;
    if (i < NB * NP) { d_r[i] = 0.f; d_c[i] = 0.f; }
    if (i == 0) { d_hinge = 0.0; d_scon = 0.0; }
}

// ---------------- row-normalize all 4 inputs ----------------
__global__ void normalize_kernel(const float* __restrict__ x1, const float* __restrict__ x2,
                                 const float* __restrict__ x3, const float* __restrict__ x4) {
    int w = (blockIdx.x * blockDim.x + threadIdx.x) >> 5;  // warp per row
    int lane = threadIdx.x & 31;
    int t = w >> 13;            // tensor 0..3
    int row = w & 8191;         // 8*1024 rows
    const float* src = (t == 0) ? x1 : (t == 1) ? x2 : (t == 2) ? x3 : x4;
    const float2* p = (const float2*)(src + (size_t)row * ND);
    float2 v = p[lane];
    float ss = v.x * v.x + v.y * v.y;
    #pragma unroll
    for (int o = 16; o; o >>= 1) ss += __shfl_xor_sync(0xFFFFFFFFu, ss, o);
    float nrm = sqrtf(ss);
    float sc = 1.0f / fmaxf(nrm, 1e-12f);
    float2* q = (float2*)(d_feat[t] + (size_t)row * ND);
    q[lane] = make_float2(v.x * sc, v.y * sc);
}

// ---------------- GEMM: 64x64 tile, K=64, fp32 ----------------
// MODE 0: TL  sim -> store S into d_C, accumulate row+col sums
// MODE 1: TR  sim -> row sums only
// MODE 2: BL  sim -> col sums only
// MODE 3: hinge (raw inputs) -> sum relu(margin - dot)
template <int MODE>
__global__ void gemm_kernel(const float* __restrict__ Ap, const float* __restrict__ Bp,
                            int asel, int bsel) {
    __shared__ float As[64][68];
    __shared__ float Bs[64][68];
    int b = blockIdx.z;
    int rowBase = blockIdx.y * 64;
    int colBase = blockIdx.x * 64;
    const float* A = (MODE == 3) ? Ap : d_feat[asel];
    const float* Bm = (MODE == 3) ? Bp : d_feat[bsel];
    const float* Ab = A + ((size_t)b * NP + rowBase) * ND;
    const float* Bb = Bm + ((size_t)b * NP + colBase) * ND;
    int tid = threadIdx.x;  // 256

    for (int i = tid; i < 1024; i += 256) {
        int r = i >> 4, kv = (i & 15) << 2;
        float4 va = *(const float4*)(Ab + r * ND + kv);
        As[kv + 0][r] = va.x; As[kv + 1][r] = va.y; As[kv + 2][r] = va.z; As[kv + 3][r] = va.w;
        float4 vb = *(const float4*)(Bb + r * ND + kv);
        Bs[kv + 0][r] = vb.x; Bs[kv + 1][r] = vb.y; Bs[kv + 2][r] = vb.z; Bs[kv + 3][r] = vb.w;
    }
    __syncthreads();

    int ty = tid >> 4, tx = tid & 15;
    float acc[4][4];
    #pragma unroll
    for (int i = 0; i < 4; i++)
        #pragma unroll
        for (int j = 0; j < 4; j++) acc[i][j] = 0.f;

    #pragma unroll 16
    for (int k = 0; k < 64; k++) {
        float4 a = *(const float4*)&As[k][ty << 2];
        float4 bb = *(const float4*)&Bs[k][tx << 2];
        float av[4] = {a.x, a.y, a.z, a.w};
        float bv[4] = {bb.x, bb.y, bb.z, bb.w};
        #pragma unroll
        for (int i = 0; i < 4; i++)
            #pragma unroll
            for (int j = 0; j < 4; j++) acc[i][j] = fmaf(av[i], bv[j], acc[i][j]);
    }

    if (MODE == 3) {
        float s = 0.f;
        #pragma unroll
        for (int i = 0; i < 4; i++)
            #pragma unroll
            for (int j = 0; j < 4; j++) s += fmaxf(MARGIN - acc[i][j], 0.f);
        __syncthreads();
        float* red = &As[0][0];
        red[tid] = s;
        __syncthreads();
        for (int st = 128; st; st >>= 1) {
            if (tid < st) red[tid] += red[tid + st];
            __syncthreads();
        }
        if (tid == 0) atomicAdd(&d_hinge, (double)red[0]);
        return;
    }

    float s[4][4];
    #pragma unroll
    for (int i = 0; i < 4; i++)
        #pragma unroll
        for (int j = 0; j < 4; j++) s[i][j] = __expf(GAMMA * acc[i][j]);

    if (MODE == 0) {
        float* Cp = d_C + ((size_t)b * NP + rowBase) * NP + colBase;
        #pragma unroll
        for (int i = 0; i < 4; i++)
            *(float4*)(Cp + (size_t)(ty * 4 + i) * NP + tx * 4) =
                make_float4(s[i][0], s[i][1], s[i][2], s[i][3]);
    }

    __syncthreads();  // done with As; reuse as reduction space
    float* red = &As[0][0];  // [0..63] rows, [64..127] cols
    if (tid < 128) red[tid] = 0.f;
    __syncthreads();
    if (MODE != 2) {  // row sums
        #pragma unroll
        for (int i = 0; i < 4; i++) {
            float rs = s[i][0] + s[i][1] + s[i][2] + s[i][3];
            atomicAdd(&red[ty * 4 + i], rs);
        }
    }
    if (MODE != 1) {  // col sums
        #pragma unroll
        for (int j = 0; j < 4; j++) {
            float cs = s[0][j] + s[1][j] + s[2][j] + s[3][j];
            atomicAdd(&red[64 + tx * 4 + j], cs);
        }
    }
    __syncthreads();
    if (MODE != 2 && tid < 64) atomicAdd(&d_r[b * NP + rowBase + tid], red[tid]);
    if (MODE != 1 && tid >= 64 && tid < 128)
        atomicAdd(&d_c[b * NP + colBase + (tid - 64)], red[tid]);
}

// ---------------- C = 1 - S/(c+r-S), plus transpose into d_CT ----------------
__global__ void finalize_kernel() {
    __shared__ float tile[32][33];
    int b = blockIdx.z;
    int pBase = blockIdx.y * 32, qBase = blockIdx.x * 32;
    int tx = threadIdx.x, ty = threadIdx.y;  // (32, 8)
    #pragma unroll
    for (int j = 0; j < 4; j++) {
        int p = pBase + ty + j * 8;
        int q = qBase + tx;
        size_t idx = ((size_t)b * NP + p) * NP + q;
        float S = d_C[idx];
        float Cv = 1.f - S / (d_r[b * NP + p] + d_c[b * NP + q] - S);
        d_C[idx] = Cv;
        tile[ty + j * 8][tx] = Cv;
    }
    __syncthreads();
    #pragma unroll
    for (int j = 0; j < 4; j++) {
        int q = qBase + ty + j * 8;
        int p = pBase + tx;
        d_CT[((size_t)b * NP + q) * NP + p] = tile[tx][ty + j * 8];
    }
}

// ---------------- fused softmin: warp per row ----------------
// mode 0: init (h=0, write dst)
// mode 1: loop (h = dual/eps, averaged update into dst)
// mode 2: final (h = dual/eps, accumulate sum into d_scon)
__global__ void softmin_kernel(int src, int dst, float eps, int mode) {
    int w = (blockIdx.x * blockDim.x + threadIdx.x) >> 5;
    int lane = threadIdx.x & 31;
    int side = w >> 13;          // 0: ft (rows of C), 1: gt (rows of CT)
    int idx = w & 8191;          // b*1024 + p
    int b = idx >> 10;
    const float4* row = (const float4*)((side == 0 ? d_C : d_CT) + (size_t)idx * NP);
    const float4* h4 = (const float4*)((side == 0 ? d_g[src] : d_f[src]) + b * NP);

    float u[32];
    float m = -3.4e38f;
    #pragma unroll
    for (int j = 0; j < 8; j++) {
        float4 cv = row[j * 32 + lane];
        float4 hv;
        if (mode == 0) hv = make_float4(0.f, 0.f, 0.f, 0.f);
        else hv = h4[j * 32 + lane];
        u[4 * j + 0] = hv.x - cv.x;
        u[4 * j + 1] = hv.y - cv.y;
        u[4 * j + 2] = hv.z - cv.z;
        u[4 * j + 3] = hv.w - cv.w;
        m = fmaxf(m, fmaxf(fmaxf(u[4 * j + 0], u[4 * j + 1]),
                           fmaxf(u[4 * j + 2], u[4 * j + 3])));
    }
    #pragma unroll
    for (int o = 16; o; o >>= 1) m = fmaxf(m, __shfl_xor_sync(0xFFFFFFFFu, m, o));
    float inv = 1.0f / eps;
    float sum = 0.f;
    #pragma unroll
    for (int i = 0; i < 32; i++) sum += __expf((u[i] - m) * inv);
    #pragma unroll
    for (int o = 16; o; o >>= 1) sum += __shfl_xor_sync(0xFFFFFFFFu, sum, o);

    if (lane == 0) {
        float val = -(m + eps * logf(sum));
        if (mode == 2) {
            atomicAdd(&d_scon, (double)val);
        } else {
            if (mode == 1) {
                float prev = (side == 0 ? d_f[src] : d_g[src])[idx];
                val = 0.5f * (prev + val);
            }
            (side == 0 ? d_f[dst] : d_g[dst])[idx] = val;
        }
    }
}

// ---------------- output writer ----------------
__global__ void write_out(float* out) {
    if (threadIdx.x == 0) {
        out[0] = (float)d_hinge;
        out[1] = (float)(d_scon / 8.0);
    }
}

// ---------------- launch ----------------
extern "C" void kernel_launch(void* const* d_in, const int* in_sizes, int n_in,
                              void* d_out, int out_size) {
    (void)in_sizes; (void)n_in; (void)out_size;
    const float* x1 = (const float*)d_in[0];
    const float* x2 = (const float*)d_in[1];
    const float* x3 = (const float*)d_in[2];
    const float* x4 = (const float*)d_in[3];
    float* out = (float*)d_out;

    // geomloss epsilon schedule (p=2, diam=3, blur=0.05, scaling=0.5)
    double pexp = 2.0, diam = 3.0, blur = 0.05, scal = 0.5;
    float eps_list[16];
    int n_eps = 0;
    eps_list[n_eps++] = (float)pow(diam, pexp);
    for (double v = pexp * log(diam); v > pexp * log(blur); v += pexp * log(scal))
        eps_list[n_eps++] = (float)exp(v);
    eps_list[n_eps++] = (float)pow(blur, pexp);   // n_eps == 8

    reset_kernel<<<32, 256>>>();
    normalize_kernel<<<4096, 256>>>(x1, x2, x3, x4);

    dim3 gg(16, 16, NB);
    gemm_kernel<0><<<gg, 256>>>(nullptr, nullptr, 0, 1);  // TL: x1n . x2n (store + r + c)
    gemm_kernel<1><<<gg, 256>>>(nullptr, nullptr, 0, 3);  // TR: x1n . x4n (r only)
    gemm_kernel<2><<<gg, 256>>>(nullptr, nullptr, 2, 1);  // BL: x3n . x2n (c only)
    gemm_kernel<3><<<gg, 256>>>(x3, x4, 0, 0);            // hinge (raw)

    finalize_kernel<<<dim3(32, 32, NB), dim3(32, 8)>>>();

    // Sinkhorn
    softmin_kernel<<<2048, 256>>>(0, 0, eps_list[0], 0);  // init -> buf0
    int cur = 0;
    for (int i = 0; i < n_eps; i++) {
        softmin_kernel<<<2048, 256>>>(cur, 1 - cur, eps_list[i], 1);
        cur = 1 - cur;
    }
    softmin_kernel<<<2048, 256>>>(cur, cur, eps_list[n_eps - 1], 2);  // final extrapolation

    write_out<<<1, 1>>>(out);
}

// round 3
// speedup vs baseline: 1.1782x; 1.1782x over previous
#include <cuda_runtime.h>
#include <math.h>

#define NB 8
#define NP 1024
#define ND 64
#define GAMMA 10.0f
#define MARGIN 0.1f

// ---------------- device scratch (no allocs allowed) ----------------
__device__ float d_feat[4][NB * NP * ND];      // normalized x1..x4 (8 MB)
__device__ float d_C[NB * NP * NP];            // cost TL block (32 MB)
__device__ float d_CT[NB * NP * NP];           // transposed cost (32 MB)
__device__ float d_r[NB * NP];                 // row sums of sim
__device__ float d_c[NB * NP];                 // col sums of sim
__device__ float d_f[2][NB * NP];              // dual f ping-pong
__device__ float d_g[2][NB * NP];              // dual g ping-pong
__device__ double d_hinge;
__device__ double d_scon;

// ---------------- reset ----------------
__global__ void reset_kernel() {
    int i = blockIdx.x * blockDim.x + threadIdx.x;
    if (i < NB * NP) { d_r[i] = 0.f; d_c[i] = 0.f; }
    if (i == 0) { d_hinge = 0.0; d_scon = 0.0; }
}

// ---------------- row-normalize all 4 inputs ----------------
__global__ void normalize_kernel(const float* __restrict__ x1, const float* __restrict__ x2,
                                 const float* __restrict__ x3, const float* __restrict__ x4) {
    int w = (blockIdx.x * blockDim.x + threadIdx.x) >> 5;  // warp per row
    int lane = threadIdx.x & 31;
    int t = w >> 13;            // tensor 0..3
    int row = w & 8191;         // 8*1024 rows
    const float* src = (t == 0) ? x1 : (t == 1) ? x2 : (t == 2) ? x3 : x4;
    const float2* p = (const float2*)(src + (size_t)row * ND);
    float2 v = p[lane];
    float ss = v.x * v.x + v.y * v.y;
    #pragma unroll
    for (int o = 16; o; o >>= 1) ss += __shfl_xor_sync(0xFFFFFFFFu, ss, o);
    float sc = 1.0f / fmaxf(sqrtf(ss), 1e-12f);
    float2* q = (float2*)(d_feat[t] + (size_t)row * ND);
    q[lane] = make_float2(v.x * sc, v.y * sc);
}

// ---------------- fused GEMM: 128x128 tile, 8x8 microtile, K=64 ----------------
// job 0: TL  sim = exp(g*x1n.x2n) -> store S into d_C, row sums -> d_r, col sums -> d_c
// job 1: TR  sim = exp(g*x1n.x4n) -> row sums -> d_r only
// job 2: BL  sim = exp(g*x3n.x2n) -> col sums -> d_c only
// job 3: hinge on raw x3.x4 -> sum relu(margin - dot) -> d_hinge
__global__ void fused_gemm(const float* __restrict__ x3, const float* __restrict__ x4) {
    extern __shared__ float sm[];
    float* As = sm;            // [64][128] k-major
    float* Bs = sm + 64 * 128; // [64][128]
    int z = blockIdx.z;
    int b = z & 7;
    int job = z >> 3;
    int rowBase = blockIdx.y * 128;
    int colBase = blockIdx.x * 128;

    const float* A;
    const float* B;
    if (job == 0)      { A = d_feat[0]; B = d_feat[1]; }
    else if (job == 1) { A = d_feat[0]; B = d_feat[3]; }
    else if (job == 2) { A = d_feat[2]; B = d_feat[1]; }
    else               { A = x3;        B = x4;        }
    const float* Ab = A + ((size_t)b * NP + rowBase) * ND;
    const float* Bb = B + ((size_t)b * NP + colBase) * ND;

    int tid = threadIdx.x;  // 256

    // stage global -> smem (transposed to k-major): 2048 float4 per matrix
    for (int i = tid; i < 2048; i += 256) {
        int r = i >> 4;
        int kv = (i & 15) << 2;
        float4 va = *(const float4*)(Ab + r * ND + kv);
        As[(kv + 0) * 128 + r] = va.x;
        As[(kv + 1) * 128 + r] = va.y;
        As[(kv + 2) * 128 + r] = va.z;
        As[(kv + 3) * 128 + r] = va.w;
        float4 vb = *(const float4*)(Bb + r * ND + kv);
        Bs[(kv + 0) * 128 + r] = vb.x;
        Bs[(kv + 1) * 128 + r] = vb.y;
        Bs[(kv + 2) * 128 + r] = vb.z;
        Bs[(kv + 3) * 128 + r] = vb.w;
    }
    __syncthreads();

    int ty = tid >> 4, tx = tid & 15;
    // thread's rows: ty*4+{0..3}, 64+ty*4+{0..3}; cols: tx*4+{0..3}, 64+tx*4+{0..3}
    float acc[8][8];
    #pragma unroll
    for (int i = 0; i < 8; i++)
        #pragma unroll
        for (int j = 0; j < 8; j++) acc[i][j] = 0.f;

    #pragma unroll 8
    for (int k = 0; k < 64; k++) {
        float4 a0 = *(const float4*)&As[k * 128 + ty * 4];
        float4 a1 = *(const float4*)&As[k * 128 + 64 + ty * 4];
        float4 b0 = *(const float4*)&Bs[k * 128 + tx * 4];
        float4 b1 = *(const float4*)&Bs[k * 128 + 64 + tx * 4];
        float av[8] = {a0.x, a0.y, a0.z, a0.w, a1.x, a1.y, a1.z, a1.w};
        float bv[8] = {b0.x, b0.y, b0.z, b0.w, b1.x, b1.y, b1.z, b1.w};
        #pragma unroll
        for (int i = 0; i < 8; i++)
            #pragma unroll
            for (int j = 0; j < 8; j++)
                acc[i][j] = fmaf(av[i], bv[j], acc[i][j]);
    }

    if (job == 3) {
        // hinge
        float s = 0.f;
        #pragma unroll
        for (int i = 0; i < 8; i++)
            #pragma unroll
            for (int j = 0; j < 8; j++)
                s += fmaxf(MARGIN - acc[i][j], 0.f);
        #pragma unroll
        for (int o = 16; o; o >>= 1) s += __shfl_xor_sync(0xFFFFFFFFu, s, o);
        __syncthreads();
        if ((tid & 31) == 0) sm[tid >> 5] = s;
        __syncthreads();
        if (tid == 0) {
            float t = 0.f;
            #pragma unroll
            for (int w = 0; w < 8; w++) t += sm[w];
            atomicAdd(&d_hinge, (double)t);
        }
        return;
    }

    // sim = exp(gamma * dot)
    float s[8][8];
    #pragma unroll
    for (int i = 0; i < 8; i++)
        #pragma unroll
        for (int j = 0; j < 8; j++) s[i][j] = __expf(GAMMA * acc[i][j]);

    if (job == 0) {
        // store S tile to d_C
        #pragma unroll
        for (int i = 0; i < 8; i++) {
            int row = rowBase + ((i < 4) ? (ty * 4 + i) : (64 + ty * 4 + i - 4));
            float* Cp = d_C + ((size_t)b * NP + row) * NP + colBase;
            *(float4*)(Cp + tx * 4)      = make_float4(s[i][0], s[i][1], s[i][2], s[i][3]);
            *(float4*)(Cp + 64 + tx * 4) = make_float4(s[i][4], s[i][5], s[i][6], s[i][7]);
        }
    }

    // row sums (jobs 0,1): reduce over 16 tx lanes (all within a 16-lane shfl group)
    if (job <= 1) {
        #pragma unroll
        for (int i = 0; i < 8; i++) {
            float rs = 0.f;
            #pragma unroll
            for (int j = 0; j < 8; j++) rs += s[i][j];
            #pragma unroll
            for (int o = 8; o; o >>= 1) rs += __shfl_xor_sync(0xFFFFFFFFu, rs, o);
            if (tx == 0) {
                int row = rowBase + ((i < 4) ? (ty * 4 + i) : (64 + ty * 4 + i - 4));
                atomicAdd(&d_r[b * NP + row], rs);
            }
        }
    }

    // col sums (jobs 0,2): combine 2 ty in warp via xor16, then shared atomics over 8 warps
    __syncthreads();                 // done with As/Bs; reuse sm[0..127]
    if (tid < 128) sm[tid] = 0.f;
    __syncthreads();
    if (job == 0 || job == 2) {
        #pragma unroll
        for (int j = 0; j < 8; j++) {
            float cs = 0.f;
            #pragma unroll
            for (int i = 0; i < 8; i++) cs += s[i][j];
            cs += __shfl_xor_sync(0xFFFFFFFFu, cs, 16);
            if ((tid & 31) < 16) {
                int col = (j < 4) ? (tx * 4 + j) : (64 + tx * 4 + j - 4);
                atomicAdd(&sm[col], cs);
            }
        }
    }
    __syncthreads();
    if ((job == 0 || job == 2) && tid < 128)
        atomicAdd(&d_c[b * NP + colBase + tid], sm[tid]);
}

// ---------------- C = 1 - S/(c+r-S), plus transpose into d_CT ----------------
__global__ void finalize_kernel() {
    __shared__ float tile[32][33];
    int b = blockIdx.z;
    int pBase = blockIdx.y * 32, qBase = blockIdx.x * 32;
    int tx = threadIdx.x, ty = threadIdx.y;  // (32, 8)
    #pragma unroll
    for (int j = 0; j < 4; j++) {
        int p = pBase + ty + j * 8;
        int q = qBase + tx;
        size_t idx = ((size_t)b * NP + p) * NP + q;
        float S = d_C[idx];
        float Cv = 1.f - S / (d_r[b * NP + p] + d_c[b * NP + q] - S);
        d_C[idx] = Cv;
        tile[ty + j * 8][tx] = Cv;
    }
    __syncthreads();
    #pragma unroll
    for (int j = 0; j < 4; j++) {
        int q = qBase + ty + j * 8;
        int p = pBase + tx;
        d_CT[((size_t)b * NP + q) * NP + p] = tile[tx][ty + j * 8];
    }
}

// ---------------- fused softmin: warp per row ----------------
// mode 0: init (h=0, write dst)
// mode 1: loop (h = dual/eps, averaged update into dst)
// mode 2: final (h = dual/eps, accumulate sum into d_scon)
__global__ void softmin_kernel(int src, int dst, float eps, int mode) {
    int w = (blockIdx.x * blockDim.x + threadIdx.x) >> 5;
    int lane = threadIdx.x & 31;
    int side = w >> 13;          // 0: ft (rows of C), 1: gt (rows of CT)
    int idx = w & 8191;          // b*1024 + p
    int b = idx >> 10;
    const float4* row = (const float4*)((side == 0 ? d_C : d_CT) + (size_t)idx * NP);
    const float4* h4 = (const float4*)((side == 0 ? d_g[src] : d_f[src]) + b * NP);

    float u[32];
    float m = -3.4e38f;
    #pragma unroll
    for (int j = 0; j < 8; j++) {
        float4 cv = row[j * 32 + lane];
        float4 hv;
        if (mode == 0) hv = make_float4(0.f, 0.f, 0.f, 0.f);
        else hv = h4[j * 32 + lane];
        u[4 * j + 0] = hv.x - cv.x;
        u[4 * j + 1] = hv.y - cv.y;
        u[4 * j + 2] = hv.z - cv.z;
        u[4 * j + 3] = hv.w - cv.w;
        m = fmaxf(m, fmaxf(fmaxf(u[4 * j + 0], u[4 * j + 1]),
                           fmaxf(u[4 * j + 2], u[4 * j + 3])));
    }
    #pragma unroll
    for (int o = 16; o; o >>= 1) m = fmaxf(m, __shfl_xor_sync(0xFFFFFFFFu, m, o));
    float inv = 1.0f / eps;
    float sum = 0.f;
    #pragma unroll
    for (int i = 0; i < 32; i++) sum += __expf((u[i] - m) * inv);
    #pragma unroll
    for (int o = 16; o; o >>= 1) sum += __shfl_xor_sync(0xFFFFFFFFu, sum, o);

    if (lane == 0) {
        float val = -(m + eps * logf(sum));
        if (mode == 2) {
            atomicAdd(&d_scon, (double)val);
        } else {
            if (mode == 1) {
                float prev = (side == 0 ? d_f[src] : d_g[src])[idx];
                val = 0.5f * (prev + val);
            }
            (side == 0 ? d_f[dst] : d_g[dst])[idx] = val;
        }
    }
}

// ---------------- output writer ----------------
__global__ void write_out(float* out) {
    if (threadIdx.x == 0) {
        out[0] = (float)d_hinge;
        out[1] = (float)(d_scon / 8.0);
    }
}

// ---------------- launch ----------------
extern "C" void kernel_launch(void* const* d_in, const int* in_sizes, int n_in,
                              void* d_out, int out_size) {
    (void)in_sizes; (void)n_in; (void)out_size;
    const float* x1 = (const float*)d_in[0];
    const float* x2 = (const float*)d_in[1];
    const float* x3 = (const float*)d_in[2];
    const float* x4 = (const float*)d_in[3];
    float* out = (float*)d_out;

    // geomloss epsilon schedule (p=2, diam=3, blur=0.05, scaling=0.5)
    double pexp = 2.0, diam = 3.0, blur = 0.05, scal = 0.5;
    float eps_list[16];
    int n_eps = 0;
    eps_list[n_eps++] = (float)pow(diam, pexp);
    for (double v = pexp * log(diam); v > pexp * log(blur); v += pexp * log(scal))
        eps_list[n_eps++] = (float)exp(v);
    eps_list[n_eps++] = (float)pow(blur, pexp);   // n_eps == 8

    cudaFuncSetAttribute(fused_gemm, cudaFuncAttributeMaxDynamicSharedMemorySize, 65536);

    reset_kernel<<<32, 256>>>();
    normalize_kernel<<<4096, 256>>>(x1, x2, x3, x4);

    fused_gemm<<<dim3(8, 8, 32), 256, 65536>>>(x3, x4);

    finalize_kernel<<<dim3(32, 32, NB), dim3(32, 8)>>>();

    // Sinkhorn
    softmin_kernel<<<2048, 256>>>(0, 0, eps_list[0], 0);  // init -> buf0
    int cur = 0;
    for (int i = 0; i < n_eps; i++) {
        softmin_kernel<<<2048, 256>>>(cur, 1 - cur, eps_list[i], 1);
        cur = 1 - cur;
    }
    softmin_kernel<<<2048, 256>>>(cur, cur, eps_list[n_eps - 1], 2);  // final extrapolation

    write_out<<<1, 1>>>(out);
}

// round 5
// speedup vs baseline: 1.7332x; 1.4710x over previous
#include <cuda_runtime.h>
#include <cuda_bf16.h>
#include <math.h>
#include <stdint.h>

#define NB 8
#define NP 1024
#define ND 64
#define GAMMA 10.0f
#define MARGIN 0.1f

// ================= device scratch =================
__device__ __nv_bfloat16 d_hi[6 * NB * NP * ND];   // hi split: x1n,x2n,x3n,x4n,x3raw,x4raw
__device__ __nv_bfloat16 d_lo[6 * NB * NP * ND];   // lo split
__device__ float d_C[NB * NP * NP];                // cost TL block (32 MB)
__device__ float d_CT[NB * NP * NP];               // transposed cost (32 MB)
__device__ float d_r[NB * NP];
__device__ float d_c[NB * NP];
__device__ float d_f[2][NB * NP];
__device__ float d_g[2][NB * NP];
__device__ double d_hinge;
__device__ double d_scon;

// ================= helpers =================
__device__ __forceinline__ uint32_t smem_u32(const void* p) {
    uint32_t a;
    asm("{ .reg .u64 t; cvta.to.shared.u64 t, %1; cvt.u32.u64 %0, t; }" : "=r"(a) : "l"(p));
    return a;
}
__device__ __forceinline__ uint32_t sw128(uint32_t off) { return off ^ ((off >> 3) & 0x70); }

__device__ __forceinline__ void ldsm_x4(uint32_t* r, uint32_t addr) {
    asm volatile("ldmatrix.sync.aligned.m8n8.x4.shared.b16 {%0,%1,%2,%3}, [%4];"
        : "=r"(r[0]), "=r"(r[1]), "=r"(r[2]), "=r"(r[3]) : "r"(addr));
}
__device__ __forceinline__ void ldsm_x2(uint32_t* r, uint32_t addr) {
    asm volatile("ldmatrix.sync.aligned.m8n8.x2.shared.b16 {%0,%1}, [%2];"
        : "=r"(r[0]), "=r"(r[1]) : "r"(addr));
}
__device__ __forceinline__ void mma_bf16(float* d, const uint32_t* a, const uint32_t* b) {
    asm volatile("mma.sync.aligned.m16n8k16.row.col.f32.bf16.bf16.f32 "
        "{%0,%1,%2,%3}, {%4,%5,%6,%7}, {%8,%9}, {%0,%1,%2,%3};"
        : "+f"(d[0]), "+f"(d[1]), "+f"(d[2]), "+f"(d[3])
        : "r"(a[0]), "r"(a[1]), "r"(a[2]), "r"(a[3]), "r"(b[0]), "r"(b[1]));
}

// ================= reset =================
__global__ void reset_kernel() {
    int i = blockIdx.x * blockDim.x + threadIdx.x;
    if (i < NB * NP) { d_r[i] = 0.f; d_c[i] = 0.f; }
    if (i == 0) { d_hinge = 0.0; d_scon = 0.0; }
}

// ================= normalize + hi/lo split (6 tensors) =================
__global__ void norm_split(const float* __restrict__ x1, const float* __restrict__ x2,
                           const float* __restrict__ x3, const float* __restrict__ x4) {
    int w = (blockIdx.x * blockDim.x + threadIdx.x) >> 5;  // 6*8192 warps
    int lane = threadIdx.x & 31;
    int t = w / 8192;
    int row = w - t * 8192;
    const float* src = (t == 0) ? x1 : (t == 1) ? x2 : (t == 2 || t == 4) ? x3 : x4;
    float2 v = ((const float2*)(src + (size_t)row * ND))[lane];
    if (t < 4) {
        float ss = v.x * v.x + v.y * v.y;
        #pragma unroll
        for (int o = 16; o; o >>= 1) ss += __shfl_xor_sync(0xFFFFFFFFu, ss, o);
        float sc = 1.0f / fmaxf(sqrtf(ss), 1e-12f);
        v.x *= sc; v.y *= sc;
    }
    __nv_bfloat16 hx = __float2bfloat16(v.x);
    __nv_bfloat16 hy = __float2bfloat16(v.y);
    __nv_bfloat16 lx = __float2bfloat16(v.x - __bfloat162float(hx));
    __nv_bfloat16 ly = __float2bfloat16(v.y - __bfloat162float(hy));
    size_t base = ((size_t)t * 8192 + row) * ND;
    ((__nv_bfloat162*)(d_hi + base))[lane] = __nv_bfloat162(hx, hy);
    ((__nv_bfloat162*)(d_lo + base))[lane] = __nv_bfloat162(lx, ly);
}

// ================= mma.sync fused GEMM =================
// 128x128 tile, 256 threads (8 warps in 2x4), K=64, bf16 hi/lo 3-pass split.
// job 0: TL store S + rowsum + colsum; job 1: TR rowsum; job 2: BL colsum; job 3: hinge
#define SM_AHI  0
#define SM_ALO  16384
#define SM_BHI  32768
#define SM_BLO  49152
#define SM_RED  65536
#define SM_TOT  (65536 + 256)

__global__ void __launch_bounds__(256, 2) mma_gemm() {
    extern __shared__ char smem[];
    uint32_t sb = smem_u32(smem);
    int tid = threadIdx.x;
    int wid = tid >> 5;
    int lane = tid & 31;
    int warp_m = wid >> 2;     // 0..1
    int warp_n = wid & 3;      // 0..3
    int z = blockIdx.z;
    int b = z & 7;
    int job = z >> 3;
    int rowBase = blockIdx.y * 128;
    int colBase = blockIdx.x * 128;

    // ---- stage global -> smem (coalesced, swizzled) ----
    const int TA[4] = {0, 0, 2, 4};
    const int TB[4] = {1, 3, 1, 5};
    {
        size_t aoff = ((size_t)TA[job] * 8192 + b * NP + rowBase) * ND;
        size_t boff = ((size_t)TB[job] * 8192 + b * NP + colBase) * ND;
        const uint4* srcs[4] = {
            (const uint4*)(d_hi + aoff), (const uint4*)(d_lo + aoff),
            (const uint4*)(d_hi + boff), (const uint4*)(d_lo + boff)};
        char* dsts[4] = {smem + SM_AHI, smem + SM_ALO, smem + SM_BHI, smem + SM_BLO};
        #pragma unroll
        for (int m = 0; m < 4; m++) {
            const uint4* s = srcs[m];
            char* d = dsts[m];
            #pragma unroll
            for (int it = 0; it < 4; it++) {
                int idx = it * 256 + tid;          // 1024 uint4 = 128 rows x 8 chunks
                int r = idx >> 3, c = idx & 7;
                *(uint4*)(d + sw128(r * 128 + c * 16)) = s[idx];
            }
        }
    }
    __syncthreads();

    // ---- MMA mainloop: 3 passes (hi*hi, hi*lo, lo*hi) x 4 k-steps ----
    float acc[4][4][4];
    #pragma unroll
    for (int mi = 0; mi < 4; mi++)
        #pragma unroll
        for (int ni = 0; ni < 4; ni++)
            #pragma unroll
            for (int v = 0; v < 4; v++) acc[mi][ni][v] = 0.f;

    const uint32_t passA[3] = {sb + SM_AHI, sb + SM_AHI, sb + SM_ALO};
    const uint32_t passB[3] = {sb + SM_BHI, sb + SM_BLO, sb + SM_BHI};

    int mrow = warp_m * 64 + (lane & 15);
    int nrow = warp_n * 32 + (lane & 7);
    int l7 = lane & 7;

    #pragma unroll
    for (int p = 0; p < 3; p++) {
        uint32_t abase = passA[p], bbase = passB[p];
        #pragma unroll
        for (int k = 0; k < 4; k++) {
            uint32_t Af[4][4], Bf[4][2];
            int achunk = (2 * k + (lane >> 4)) ^ l7;          // swizzled chunk (m&7 == lane&7)
            int bchunk = (2 * k + ((lane >> 3) & 1)) ^ l7;
            #pragma unroll
            for (int mi = 0; mi < 4; mi++)
                ldsm_x4(Af[mi], abase + (mrow + mi * 16) * 128 + achunk * 16);
            #pragma unroll
            for (int ni = 0; ni < 4; ni++)
                ldsm_x2(Bf[ni], bbase + (nrow + ni * 8) * 128 + bchunk * 16);
            #pragma unroll
            for (int mi = 0; mi < 4; mi++)
                #pragma unroll
                for (int ni = 0; ni < 4; ni++)
                    mma_bf16(acc[mi][ni], Af[mi], Bf[ni]);
        }
    }

    // ---- epilogue ----
    int g = lane >> 2, t4 = lane & 3;

    if (job == 3) {
        float h = 0.f;
        #pragma unroll
        for (int mi = 0; mi < 4; mi++)
            #pragma unroll
            for (int ni = 0; ni < 4; ni++)
                #pragma unroll
                for (int v = 0; v < 4; v++)
                    h += fmaxf(MARGIN - acc[mi][ni][v], 0.f);
        #pragma unroll
        for (int o = 16; o; o >>= 1) h += __shfl_xor_sync(0xFFFFFFFFu, h, o);
        float* red = (float*)(smem + SM_RED);
        if (lane == 0) red[wid] = h;
        __syncthreads();
        if (tid == 0) {
            float s = 0.f;
            #pragma unroll
            for (int w = 0; w < 8; w++) s += red[w];
            atomicAdd(&d_hinge, (double)s);
        }
        return;
    }

    float rs[4][2], cs[4][2];
    #pragma unroll
    for (int i = 0; i < 4; i++) { rs[i][0] = rs[i][1] = cs[i][0] = cs[i][1] = 0.f; }

    #pragma unroll
    for (int mi = 0; mi < 4; mi++) {
        int row = rowBase + warp_m * 64 + mi * 16 + g;
        #pragma unroll
        for (int ni = 0; ni < 4; ni++) {
            float e0 = __expf(GAMMA * acc[mi][ni][0]);
            float e1 = __expf(GAMMA * acc[mi][ni][1]);
            float e2 = __expf(GAMMA * acc[mi][ni][2]);
            float e3 = __expf(GAMMA * acc[mi][ni][3]);
            if (job == 0) {
                int col = colBase + warp_n * 32 + ni * 8 + t4 * 2;
                float* Cp = d_C + ((size_t)b * NP + row) * NP + col;
                *(float2*)Cp = make_float2(e0, e1);
                *(float2*)(Cp + (size_t)8 * NP) = make_float2(e2, e3);
            }
            rs[mi][0] += e0 + e1;  rs[mi][1] += e2 + e3;
            cs[ni][0] += e0 + e2;  cs[ni][1] += e1 + e3;
        }
    }

    if (job <= 1) {
        #pragma unroll
        for (int mi = 0; mi < 4; mi++) {
            float r0 = rs[mi][0], r1 = rs[mi][1];
            r0 += __shfl_xor_sync(0xFFFFFFFFu, r0, 1);
            r0 += __shfl_xor_sync(0xFFFFFFFFu, r0, 2);
            r1 += __shfl_xor_sync(0xFFFFFFFFu, r1, 1);
            r1 += __shfl_xor_sync(0xFFFFFFFFu, r1, 2);
            if (t4 == 0) {
                int row = rowBase + warp_m * 64 + mi * 16 + g;
                atomicAdd(&d_r[b * NP + row], r0);
                atomicAdd(&d_r[b * NP + row + 8], r1);
            }
        }
    }
    if (job == 0 || job == 2) {
        #pragma unroll
        for (int ni = 0; ni < 4; ni++) {
            float c0 = cs[ni][0], c1 = cs[ni][1];
            c0 += __shfl_xor_sync(0xFFFFFFFFu, c0, 4);
            c0 += __shfl_xor_sync(0xFFFFFFFFu, c0, 8);
            c0 += __shfl_xor_sync(0xFFFFFFFFu, c0, 16);
            c1 += __shfl_xor_sync(0xFFFFFFFFu, c1, 4);
            c1 += __shfl_xor_sync(0xFFFFFFFFu, c1, 8);
            c1 += __shfl_xor_sync(0xFFFFFFFFu, c1, 16);
            if (lane < 4) {
                int col = colBase + warp_n * 32 + ni * 8 + lane * 2;
                atomicAdd(&d_c[b * NP + col], c0);
                atomicAdd(&d_c[b * NP + col + 1], c1);
            }
        }
    }
}

// ================= finalize: C = 1 - S/(r+c-S), write C and CT =================
__global__ void finalize_kernel() {
    __shared__ float tile[64][68];
    int b = blockIdx.z;
    int pBase = blockIdx.y * 64, qBase = blockIdx.x * 64;
    int tid = threadIdx.x;  // 256
    #pragma unroll
    for (int v = 0; v < 4; v++) {
        int f4 = v * 256 + tid;
        int row = f4 >> 4;
        int c4 = f4 & 15;
        int p = pBase + row;
        size_t idx = ((size_t)b * NP + p) * NP + qBase + c4 * 4;
        float4 S = *(const float4*)(d_C + idx);
        float rp = d_r[b * NP + p];
        float4 cq = *(const float4*)(d_c + b * NP + qBase + c4 * 4);
        float4 C;
        C.x = 1.f - __fdividef(S.x, rp + cq.x - S.x);
        C.y = 1.f - __fdividef(S.y, rp + cq.y - S.y);
        C.z = 1.f - __fdividef(S.z, rp + cq.z - S.z);
        C.w = 1.f - __fdividef(S.w, rp + cq.w - S.w);
        *(float4*)(d_C + idx) = C;
        *(float4*)&tile[row][c4 * 4] = C;
    }
    __syncthreads();
    #pragma unroll
    for (int v = 0; v < 4; v++) {
        int f4 = v * 256 + tid;
        int qr = f4 >> 4;
        int p4 = f4 & 15;
        float4 o;
        o.x = tile[p4 * 4 + 0][qr];
        o.y = tile[p4 * 4 + 1][qr];
        o.z = tile[p4 * 4 + 2][qr];
        o.w = tile[p4 * 4 + 3][qr];
        *(float4*)(d_CT + ((size_t)b * NP + qBase + qr) * NP + pBase + p4 * 4) = o;
    }
}

// ================= fused softmin =================
__global__ void softmin_kernel(int src, int dst, float eps, int mode) {
    int w = (blockIdx.x * blockDim.x + threadIdx.x) >> 5;
    int lane = threadIdx.x & 31;
    int side = w >> 13;
    int idx = w & 8191;
    int b = idx >> 10;
    const float4* row = (const float4*)((side == 0 ? d_C : d_CT) + (size_t)idx * NP);
    const float4* h4 = (const float4*)((side == 0 ? d_g[src] : d_f[src]) + b * NP);

    float u[32];
    float m = -3.4e38f;
    #pragma unroll
    for (int j = 0; j < 8; j++) {
        float4 cv = row[j * 32 + lane];
        float4 hv;
        if (mode == 0) hv = make_float4(0.f, 0.f, 0.f, 0.f);
        else hv = h4[j * 32 + lane];
        u[4 * j + 0] = hv.x - cv.x;
        u[4 * j + 1] = hv.y - cv.y;
        u[4 * j + 2] = hv.z - cv.z;
        u[4 * j + 3] = hv.w - cv.w;
        m = fmaxf(m, fmaxf(fmaxf(u[4 * j], u[4 * j + 1]), fmaxf(u[4 * j + 2], u[4 * j + 3])));
    }
    #pragma unroll
    for (int o = 16; o; o >>= 1) m = fmaxf(m, __shfl_xor_sync(0xFFFFFFFFu, m, o));
    float inv = 1.0f / eps;
    float s0 = 0, s1 = 0, s2 = 0, s3 = 0;
    #pragma unroll
    for (int i = 0; i < 8; i++) {
        s0 += __expf((u[4 * i + 0] - m) * inv);
        s1 += __expf((u[4 * i + 1] - m) * inv);
        s2 += __expf((u[4 * i + 2] - m) * inv);
        s3 += __expf((u[4 * i + 3] - m) * inv);
    }
    float sum = (s0 + s1) + (s2 + s3);
    #pragma unroll
    for (int o = 16; o; o >>= 1) sum += __shfl_xor_sync(0xFFFFFFFFu, sum, o);

    if (lane == 0) {
        float val = -(m + eps * logf(sum));
        if (mode == 2) {
            atomicAdd(&d_scon, (double)val);
        } else {
            if (mode == 1) {
                float prev = (side == 0 ? d_f[src] : d_g[src])[idx];
                val = 0.5f * (prev + val);
            }
            (side == 0 ? d_f[dst] : d_g[dst])[idx] = val;
        }
    }
}

// ================= output =================
__global__ void write_out(float* out) {
    if (threadIdx.x == 0) {
        out[0] = (float)d_hinge;
        out[1] = (float)(d_scon / 8.0);
    }
}

// ================= launch =================
extern "C" void kernel_launch(void* const* d_in, const int* in_sizes, int n_in,
                              void* d_out, int out_size) {
    (void)in_sizes; (void)n_in; (void)out_size;
    const float* x1 = (const float*)d_in[0];
    const float* x2 = (const float*)d_in[1];
    const float* x3 = (const float*)d_in[2];
    const float* x4 = (const float*)d_in[3];
    float* out = (float*)d_out;

    double pexp = 2.0, diam = 3.0, blur = 0.05, scal = 0.5;
    float eps_list[16];
    int n_eps = 0;
    eps_list[n_eps++] = (float)pow(diam, pexp);
    for (double v = pexp * log(diam); v > pexp * log(blur); v += pexp * log(scal))
        eps_list[n_eps++] = (float)exp(v);
    eps_list[n_eps++] = (float)pow(blur, pexp);   // n_eps == 8

    cudaFuncSetAttribute(mma_gemm, cudaFuncAttributeMaxDynamicSharedMemorySize, SM_TOT);

    reset_kernel<<<32, 256>>>();
    norm_split<<<6144, 256>>>(x1, x2, x3, x4);

    mma_gemm<<<dim3(8, 8, 32), 256, SM_TOT>>>();

    finalize_kernel<<<dim3(16, 16, NB), 256>>>();

    softmin_kernel<<<2048, 256>>>(0, 0, eps_list[0], 0);
    int cur = 0;
    for (int i = 0; i < n_eps; i++) {
        softmin_kernel<<<2048, 256>>>(cur, 1 - cur, eps_list[i], 1);
        cur = 1 - cur;
    }
    softmin_kernel<<<2048, 256>>>(cur, cur, eps_list[n_eps - 1], 2);

    write_out<<<1, 1>>>(out);
}

// round 6
// speedup vs baseline: 1.8015x; 1.0394x over previous
#include <cuda_runtime.h>
#include <cuda_bf16.h>
#include <math.h>
#include <stdint.h>

#define NB 8
#define NP 1024
#define ND 64
#define GAMMA 10.0f
#define MARGIN 0.1f
#define QSCALE 65535.0f
#define IQSCALE (1.0f / 65535.0f)

// ================= device scratch =================
__device__ __nv_bfloat16 d_hi[6 * NB * NP * ND];     // hi split: x1n,x2n,x3n,x4n,x3raw,x4raw
__device__ __nv_bfloat16 d_lo[6 * NB * NP * ND];     // lo split (lo unused for t=4,5)
__device__ float d_C[NB * NP * NP];                  // sim S (32 MB), then dead after finalize
__device__ unsigned short d_Cq[NB * NP * NP];        // u16 cost (16 MB)
__device__ unsigned short d_CTq[NB * NP * NP];       // u16 transposed cost (16 MB)
__device__ float d_r[NB * NP];
__device__ float d_c[NB * NP];
__device__ float d_f[2][NB * NP];
__device__ float d_g[2][NB * NP];
__device__ double d_hinge;
__device__ double d_scon;

// ================= helpers =================
__device__ __forceinline__ uint32_t smem_u32(const void* p) {
    uint32_t a;
    asm("{ .reg .u64 t; cvta.to.shared.u64 t, %1; cvt.u32.u64 %0, t; }" : "=r"(a) : "l"(p));
    return a;
}
__device__ __forceinline__ uint32_t sw128(uint32_t off) { return off ^ ((off >> 3) & 0x70); }

__device__ __forceinline__ void ldsm_x4(uint32_t* r, uint32_t addr) {
    asm volatile("ldmatrix.sync.aligned.m8n8.x4.shared.b16 {%0,%1,%2,%3}, [%4];"
        : "=r"(r[0]), "=r"(r[1]), "=r"(r[2]), "=r"(r[3]) : "r"(addr));
}
__device__ __forceinline__ void ldsm_x2(uint32_t* r, uint32_t addr) {
    asm volatile("ldmatrix.sync.aligned.m8n8.x2.shared.b16 {%0,%1}, [%2];"
        : "=r"(r[0]), "=r"(r[1]) : "r"(addr));
}
__device__ __forceinline__ void mma_bf16(float* d, const uint32_t* a, const uint32_t* b) {
    asm volatile("mma.sync.aligned.m16n8k16.row.col.f32.bf16.bf16.f32 "
        "{%0,%1,%2,%3}, {%4,%5,%6,%7}, {%8,%9}, {%0,%1,%2,%3};"
        : "+f"(d[0]), "+f"(d[1]), "+f"(d[2]), "+f"(d[3])
        : "r"(a[0]), "r"(a[1]), "r"(a[2]), "r"(a[3]), "r"(b[0]), "r"(b[1]));
}
__device__ __forceinline__ unsigned short quant(float v) {
    return (unsigned short)__float2uint_rn(fminf(fmaxf(v, 0.f), 1.f) * QSCALE);
}

// ================= reset =================
__global__ void reset_kernel() {
    int i = blockIdx.x * blockDim.x + threadIdx.x;
    if (i < NB * NP) { d_r[i] = 0.f; d_c[i] = 0.f; }
    if (i == 0) { d_hinge = 0.0; d_scon = 0.0; }
}

// ================= normalize + hi/lo split (6 tensors) =================
__global__ void norm_split(const float* __restrict__ x1, const float* __restrict__ x2,
                           const float* __restrict__ x3, const float* __restrict__ x4) {
    int w = (blockIdx.x * blockDim.x + threadIdx.x) >> 5;  // 6*8192 warps
    int lane = threadIdx.x & 31;
    int t = w / 8192;
    int row = w - t * 8192;
    const float* src = (t == 0) ? x1 : (t == 1) ? x2 : (t == 2 || t == 4) ? x3 : x4;
    float2 v = ((const float2*)(src + (size_t)row * ND))[lane];
    if (t < 4) {
        float ss = v.x * v.x + v.y * v.y;
        #pragma unroll
        for (int o = 16; o; o >>= 1) ss += __shfl_xor_sync(0xFFFFFFFFu, ss, o);
        float sc = 1.0f / fmaxf(sqrtf(ss), 1e-12f);
        v.x *= sc; v.y *= sc;
    }
    __nv_bfloat16 hx = __float2bfloat16(v.x);
    __nv_bfloat16 hy = __float2bfloat16(v.y);
    size_t base = ((size_t)t * 8192 + row) * ND;
    ((__nv_bfloat162*)(d_hi + base))[lane] = __nv_bfloat162(hx, hy);
    if (t < 4) {
        __nv_bfloat16 lx = __float2bfloat16(v.x - __bfloat162float(hx));
        __nv_bfloat16 ly = __float2bfloat16(v.y - __bfloat162float(hy));
        ((__nv_bfloat162*)(d_lo + base))[lane] = __nv_bfloat162(lx, ly);
    }
}

// ================= mma.sync fused GEMM =================
// 128x128 tile, 256 threads (8 warps in 2x4), K=64, bf16 hi/lo 3-pass split.
// job 0: TL store S + rowsum + colsum; job 1: TR rowsum; job 2: BL colsum; job 3: hinge (hi only)
#define SM_AHI  0
#define SM_ALO  16384
#define SM_BHI  32768
#define SM_BLO  49152
#define SM_RED  65536
#define SM_TOT  (65536 + 256)

__global__ void __launch_bounds__(256, 2) mma_gemm() {
    extern __shared__ char smem[];
    uint32_t sb = smem_u32(smem);
    int tid = threadIdx.x;
    int wid = tid >> 5;
    int lane = tid & 31;
    int warp_m = wid >> 2;     // 0..1
    int warp_n = wid & 3;      // 0..3
    int z = blockIdx.z;
    int b = z & 7;
    int job = z >> 3;
    int rowBase = blockIdx.y * 128;
    int colBase = blockIdx.x * 128;

    // ---- stage global -> smem (coalesced, swizzled) ----
    const int TA[4] = {0, 0, 2, 4};
    const int TB[4] = {1, 3, 1, 5};
    {
        size_t aoff = ((size_t)TA[job] * 8192 + b * NP + rowBase) * ND;
        size_t boff = ((size_t)TB[job] * 8192 + b * NP + colBase) * ND;
        const uint4* sA = (const uint4*)(d_hi + aoff);
        const uint4* sB = (const uint4*)(d_hi + boff);
        #pragma unroll
        for (int it = 0; it < 4; it++) {
            int idx = it * 256 + tid;          // 1024 uint4 = 128 rows x 8 chunks
            int r = idx >> 3, c = idx & 7;
            uint32_t so = sw128(r * 128 + c * 16);
            *(uint4*)(smem + SM_AHI + so) = sA[idx];
            *(uint4*)(smem + SM_BHI + so) = sB[idx];
        }
        if (job != 3) {
            const uint4* sAl = (const uint4*)(d_lo + aoff);
            const uint4* sBl = (const uint4*)(d_lo + boff);
            #pragma unroll
            for (int it = 0; it < 4; it++) {
                int idx = it * 256 + tid;
                int r = idx >> 3, c = idx & 7;
                uint32_t so = sw128(r * 128 + c * 16);
                *(uint4*)(smem + SM_ALO + so) = sAl[idx];
                *(uint4*)(smem + SM_BLO + so) = sBl[idx];
            }
        }
    }
    __syncthreads();

    // ---- MMA mainloop: passes (hi*hi[, hi*lo, lo*hi]) x 4 k-steps ----
    float acc[4][4][4];
    #pragma unroll
    for (int mi = 0; mi < 4; mi++)
        #pragma unroll
        for (int ni = 0; ni < 4; ni++)
            #pragma unroll
            for (int v = 0; v < 4; v++) acc[mi][ni][v] = 0.f;

    const uint32_t passA[3] = {sb + SM_AHI, sb + SM_AHI, sb + SM_ALO};
    const uint32_t passB[3] = {sb + SM_BHI, sb + SM_BLO, sb + SM_BHI};

    int mrow = warp_m * 64 + (lane & 15);
    int nrow = warp_n * 32 + (lane & 7);
    int l7 = lane & 7;
    int npass = (job == 3) ? 1 : 3;

    #pragma unroll 1
    for (int p = 0; p < npass; p++) {
        uint32_t abase = passA[p], bbase = passB[p];
        #pragma unroll
        for (int k = 0; k < 4; k++) {
            uint32_t Af[4][4], Bf[4][2];
            int achunk = (2 * k + (lane >> 4)) ^ l7;          // swizzled chunk (m&7 == lane&7)
            int bchunk = (2 * k + ((lane >> 3) & 1)) ^ l7;
            #pragma unroll
            for (int mi = 0; mi < 4; mi++)
                ldsm_x4(Af[mi], abase + (mrow + mi * 16) * 128 + achunk * 16);
            #pragma unroll
            for (int ni = 0; ni < 4; ni++)
                ldsm_x2(Bf[ni], bbase + (nrow + ni * 8) * 128 + bchunk * 16);
            #pragma unroll
            for (int mi = 0; mi < 4; mi++)
                #pragma unroll
                for (int ni = 0; ni < 4; ni++)
                    mma_bf16(acc[mi][ni], Af[mi], Bf[ni]);
        }
    }

    // ---- epilogue ----
    int g = lane >> 2, t4 = lane & 3;

    if (job == 3) {
        float h = 0.f;
        #pragma unroll
        for (int mi = 0; mi < 4; mi++)
            #pragma unroll
            for (int ni = 0; ni < 4; ni++)
                #pragma unroll
                for (int v = 0; v < 4; v++)
                    h += fmaxf(MARGIN - acc[mi][ni][v], 0.f);
        #pragma unroll
        for (int o = 16; o; o >>= 1) h += __shfl_xor_sync(0xFFFFFFFFu, h, o);
        float* red = (float*)(smem + SM_RED);
        if (lane == 0) red[wid] = h;
        __syncthreads();
        if (tid == 0) {
            float s = 0.f;
            #pragma unroll
            for (int w = 0; w < 8; w++) s += red[w];
            atomicAdd(&d_hinge, (double)s);
        }
        return;
    }

    float rs[4][2], cs[4][2];
    #pragma unroll
    for (int i = 0; i < 4; i++) { rs[i][0] = rs[i][1] = cs[i][0] = cs[i][1] = 0.f; }

    #pragma unroll
    for (int mi = 0; mi < 4; mi++) {
        int row = rowBase + warp_m * 64 + mi * 16 + g;
        #pragma unroll
        for (int ni = 0; ni < 4; ni++) {
            float e0 = __expf(GAMMA * acc[mi][ni][0]);
            float e1 = __expf(GAMMA * acc[mi][ni][1]);
            float e2 = __expf(GAMMA * acc[mi][ni][2]);
            float e3 = __expf(GAMMA * acc[mi][ni][3]);
            if (job == 0) {
                int col = colBase + warp_n * 32 + ni * 8 + t4 * 2;
                float* Cp = d_C + ((size_t)b * NP + row) * NP + col;
                *(float2*)Cp = make_float2(e0, e1);
                *(float2*)(Cp + (size_t)8 * NP) = make_float2(e2, e3);
            }
            rs[mi][0] += e0 + e1;  rs[mi][1] += e2 + e3;
            cs[ni][0] += e0 + e2;  cs[ni][1] += e1 + e3;
        }
    }

    if (job <= 1) {
        #pragma unroll
        for (int mi = 0; mi < 4; mi++) {
            float r0 = rs[mi][0], r1 = rs[mi][1];
            r0 += __shfl_xor_sync(0xFFFFFFFFu, r0, 1);
            r0 += __shfl_xor_sync(0xFFFFFFFFu, r0, 2);
            r1 += __shfl_xor_sync(0xFFFFFFFFu, r1, 1);
            r1 += __shfl_xor_sync(0xFFFFFFFFu, r1, 2);
            if (t4 == 0) {
                int row = rowBase + warp_m * 64 + mi * 16 + g;
                atomicAdd(&d_r[b * NP + row], r0);
                atomicAdd(&d_r[b * NP + row + 8], r1);
            }
        }
    }
    if (job == 0 || job == 2) {
        #pragma unroll
        for (int ni = 0; ni < 4; ni++) {
            float c0 = cs[ni][0], c1 = cs[ni][1];
            c0 += __shfl_xor_sync(0xFFFFFFFFu, c0, 4);
            c0 += __shfl_xor_sync(0xFFFFFFFFu, c0, 8);
            c0 += __shfl_xor_sync(0xFFFFFFFFu, c0, 16);
            c1 += __shfl_xor_sync(0xFFFFFFFFu, c1, 4);
            c1 += __shfl_xor_sync(0xFFFFFFFFu, c1, 8);
            c1 += __shfl_xor_sync(0xFFFFFFFFu, c1, 16);
            if (lane < 4) {
                int col = colBase + warp_n * 32 + ni * 8 + lane * 2;
                atomicAdd(&d_c[b * NP + col], c0);
                atomicAdd(&d_c[b * NP + col + 1], c1);
            }
        }
    }
}

// ================= finalize: C = 1 - S/(r+c-S) -> u16 d_Cq + u16 d_CTq =================
__global__ void finalize_kernel() {
    __shared__ float tile[64][68];
    int b = blockIdx.z;
    int pBase = blockIdx.y * 64, qBase = blockIdx.x * 64;
    int tid = threadIdx.x;  // 256
    #pragma unroll
    for (int v = 0; v < 4; v++) {
        int f4 = v * 256 + tid;
        int row = f4 >> 4;
        int c4 = f4 & 15;
        int p = pBase + row;
        size_t idx = ((size_t)b * NP + p) * NP + qBase + c4 * 4;
        float4 S = *(const float4*)(d_C + idx);
        float rp = d_r[b * NP + p];
        float4 cq = *(const float4*)(d_c + b * NP + qBase + c4 * 4);
        float4 C;
        C.x = 1.f - __fdividef(S.x, rp + cq.x - S.x);
        C.y = 1.f - __fdividef(S.y, rp + cq.y - S.y);
        C.z = 1.f - __fdividef(S.z, rp + cq.z - S.z);
        C.w = 1.f - __fdividef(S.w, rp + cq.w - S.w);
        ushort4 q = make_ushort4(quant(C.x), quant(C.y), quant(C.z), quant(C.w));
        *(ushort4*)(d_Cq + idx) = q;
        *(float4*)&tile[row][c4 * 4] = C;
    }
    __syncthreads();
    #pragma unroll
    for (int v = 0; v < 4; v++) {
        int f4 = v * 256 + tid;
        int qr = f4 >> 4;
        int p4 = f4 & 15;
        ushort4 o;
        o.x = quant(tile[p4 * 4 + 0][qr]);
        o.y = quant(tile[p4 * 4 + 1][qr]);
        o.z = quant(tile[p4 * 4 + 2][qr]);
        o.w = quant(tile[p4 * 4 + 3][qr]);
        *(ushort4*)(d_CTq + ((size_t)b * NP + qBase + qr) * NP + pBase + p4 * 4) = o;
    }
}

// ================= fused softmin (u16 cost) =================
__global__ void softmin_kernel(int src, int dst, float eps, int mode) {
    int w = (blockIdx.x * blockDim.x + threadIdx.x) >> 5;
    int lane = threadIdx.x & 31;
    int side = w >> 13;
    int idx = w & 8191;
    int b = idx >> 10;
    const uint4* row = (const uint4*)((side == 0 ? d_Cq : d_CTq) + (size_t)idx * NP);
    const float4* h4 = (const float4*)((side == 0 ? d_g[src] : d_f[src]) + b * NP);

    float u[32];
    float m = -3.4e38f;
    #pragma unroll
    for (int j = 0; j < 4; j++) {
        uint4 q = row[j * 32 + lane];         // 8 u16 cost values
        float4 h0, h1;
        if (mode == 0) {
            h0 = make_float4(0.f, 0.f, 0.f, 0.f);
            h1 = h0;
        } else {
            h0 = h4[(j * 32 + lane) * 2];
            h1 = h4[(j * 32 + lane) * 2 + 1];
        }
        float* uu = u + j * 8;
        uu[0] = h0.x - (float)(q.x & 0xFFFF) * IQSCALE;
        uu[1] = h0.y - (float)(q.x >> 16) * IQSCALE;
        uu[2] = h0.z - (float)(q.y & 0xFFFF) * IQSCALE;
        uu[3] = h0.w - (float)(q.y >> 16) * IQSCALE;
        uu[4] = h1.x - (float)(q.z & 0xFFFF) * IQSCALE;
        uu[5] = h1.y - (float)(q.z >> 16) * IQSCALE;
        uu[6] = h1.z - (float)(q.w & 0xFFFF) * IQSCALE;
        uu[7] = h1.w - (float)(q.w >> 16) * IQSCALE;
        #pragma unroll
        for (int i = 0; i < 8; i++) m = fmaxf(m, uu[i]);
    }
    #pragma unroll
    for (int o = 16; o; o >>= 1) m = fmaxf(m, __shfl_xor_sync(0xFFFFFFFFu, m, o));
    float inv = 1.0f / eps;
    float s0 = 0, s1 = 0, s2 = 0, s3 = 0;
    #pragma unroll
    for (int i = 0; i < 8; i++) {
        s0 += __expf((u[4 * i + 0] - m) * inv);
        s1 += __expf((u[4 * i + 1] - m) * inv);
        s2 += __expf((u[4 * i + 2] - m) * inv);
        s3 += __expf((u[4 * i + 3] - m) * inv);
    }
    float sum = (s0 + s1) + (s2 + s3);
    #pragma unroll
    for (int o = 16; o; o >>= 1) sum += __shfl_xor_sync(0xFFFFFFFFu, sum, o);

    if (lane == 0) {
        float val = -(m + eps * logf(sum));
        if (mode == 2) {
            atomicAdd(&d_scon, (double)val);
        } else {
            if (mode == 1) {
                float prev = (side == 0 ? d_f[src] : d_g[src])[idx];
                val = 0.5f * (prev + val);
            }
            (side == 0 ? d_f[dst] : d_g[dst])[idx] = val;
        }
    }
}

// ================= output =================
__global__ void write_out(float* out) {
    if (threadIdx.x == 0) {
        out[0] = (float)d_hinge;
        out[1] = (float)(d_scon / 8.0);
    }
}

// ================= launch =================
extern "C" void kernel_launch(void* const* d_in, const int* in_sizes, int n_in,
                              void* d_out, int out_size) {
    (void)in_sizes; (void)n_in; (void)out_size;
    const float* x1 = (const float*)d_in[0];
    const float* x2 = (const float*)d_in[1];
    const float* x3 = (const float*)d_in[2];
    const float* x4 = (const float*)d_in[3];
    float* out = (float*)d_out;

    double pexp = 2.0, diam = 3.0, blur = 0.05, scal = 0.5;
    float eps_list[16];
    int n_eps = 0;
    eps_list[n_eps++] = (float)pow(diam, pexp);
    for (double v = pexp * log(diam); v > pexp * log(blur); v += pexp * log(scal))
        eps_list[n_eps++] = (float)exp(v);
    eps_list[n_eps++] = (float)pow(blur, pexp);   // n_eps == 8

    cudaFuncSetAttribute(mma_gemm, cudaFuncAttributeMaxDynamicSharedMemorySize, SM_TOT);

    reset_kernel<<<32, 256>>>();
    norm_split<<<6144, 256>>>(x1, x2, x3, x4);

    mma_gemm<<<dim3(8, 8, 32), 256, SM_TOT>>>();

    finalize_kernel<<<dim3(16, 16, NB), 256>>>();

    softmin_kernel<<<2048, 256>>>(0, 0, eps_list[0], 0);
    int cur = 0;
    for (int i = 0; i < n_eps; i++) {
        softmin_kernel<<<2048, 256>>>(cur, 1 - cur, eps_list[i], 1);
        cur = 1 - cur;
    }
    softmin_kernel<<<2048, 256>>>(cur, cur, eps_list[n_eps - 1], 2);

    write_out<<<1, 1>>>(out);
}

// round 7
// speedup vs baseline: 1.9144x; 1.0627x over previous
#include <cuda_runtime.h>
#include <cuda_bf16.h>
#include <math.h>
#include <stdint.h>

#define NB 8
#define NP 1024
#define ND 64
#define GAMMA 10.0f
#define MARGIN 0.1f
#define QSCALE 65535.0f
#define IQSCALE (1.0f / 65535.0f)

// ================= device scratch =================
__device__ __nv_bfloat16 d_hi[6 * NB * NP * ND];     // hi split: x1n,x2n,x3n,x4n,x3raw,x4raw
__device__ __nv_bfloat16 d_lo[6 * NB * NP * ND];     // lo split (lo unused for t=4,5)
__device__ float d_C[NB * NP * NP];                  // sim S (32 MB), dead after finalize
__device__ unsigned short d_Cq[NB * NP * NP];        // u16 cost (16 MB)
__device__ unsigned short d_CTq[NB * NP * NP];       // u16 transposed cost (16 MB)
__device__ float d_r[NB * NP];
__device__ float d_c[NB * NP];
__device__ float d_f[2][NB * NP];
__device__ float d_g[2][NB * NP];
__device__ double d_hinge;
__device__ double d_scon;

// ================= helpers =================
__device__ __forceinline__ uint32_t smem_u32(const void* p) {
    uint32_t a;
    asm("{ .reg .u64 t; cvta.to.shared.u64 t, %1; cvt.u32.u64 %0, t; }" : "=r"(a) : "l"(p));
    return a;
}
__device__ __forceinline__ uint32_t sw128(uint32_t off) { return off ^ ((off >> 3) & 0x70); }

__device__ __forceinline__ void ldsm_x4(uint32_t* r, uint32_t addr) {
    asm volatile("ldmatrix.sync.aligned.m8n8.x4.shared.b16 {%0,%1,%2,%3}, [%4];"
        : "=r"(r[0]), "=r"(r[1]), "=r"(r[2]), "=r"(r[3]) : "r"(addr));
}
__device__ __forceinline__ void ldsm_x2(uint32_t* r, uint32_t addr) {
    asm volatile("ldmatrix.sync.aligned.m8n8.x2.shared.b16 {%0,%1}, [%2];"
        : "=r"(r[0]), "=r"(r[1]) : "r"(addr));
}
__device__ __forceinline__ void mma_bf16(float* d, const uint32_t* a, const uint32_t* b) {
    asm volatile("mma.sync.aligned.m16n8k16.row.col.f32.bf16.bf16.f32 "
        "{%0,%1,%2,%3}, {%4,%5,%6,%7}, {%8,%9}, {%0,%1,%2,%3};"
        : "+f"(d[0]), "+f"(d[1]), "+f"(d[2]), "+f"(d[3])
        : "r"(a[0]), "r"(a[1]), "r"(a[2]), "r"(a[3]), "r"(b[0]), "r"(b[1]));
}
__device__ __forceinline__ unsigned short quant(float v) {
    return (unsigned short)__float2uint_rn(fminf(fmaxf(v, 0.f), 1.f) * QSCALE);
}

// ================= reset =================
__global__ void reset_kernel() {
    int i = blockIdx.x * blockDim.x + threadIdx.x;
    if (i < NB * NP) { d_r[i] = 0.f; d_c[i] = 0.f; }
    if (i == 0) { d_hinge = 0.0; d_scon = 0.0; }
}

// ================= normalize + hi/lo split =================
__global__ void norm_split(const float* __restrict__ x1, const float* __restrict__ x2,
                           const float* __restrict__ x3, const float* __restrict__ x4) {
    int w = (blockIdx.x * blockDim.x + threadIdx.x) >> 5;
    int lane = threadIdx.x & 31;
    int t = w / 8192;
    int row = w - t * 8192;
    const float* src = (t == 0) ? x1 : (t == 1) ? x2 : (t == 2 || t == 4) ? x3 : x4;
    float2 v = ((const float2*)(src + (size_t)row * ND))[lane];
    if (t < 4) {
        float ss = v.x * v.x + v.y * v.y;
        #pragma unroll
        for (int o = 16; o; o >>= 1) ss += __shfl_xor_sync(0xFFFFFFFFu, ss, o);
        float sc = 1.0f / fmaxf(sqrtf(ss), 1e-12f);
        v.x *= sc; v.y *= sc;
    }
    __nv_bfloat16 hx = __float2bfloat16(v.x);
    __nv_bfloat16 hy = __float2bfloat16(v.y);
    size_t base = ((size_t)t * 8192 + row) * ND;
    ((__nv_bfloat162*)(d_hi + base))[lane] = __nv_bfloat162(hx, hy);
    if (t < 4) {
        __nv_bfloat16 lx = __float2bfloat16(v.x - __bfloat162float(hx));
        __nv_bfloat16 ly = __float2bfloat16(v.y - __bfloat162float(hy));
        ((__nv_bfloat162*)(d_lo + base))[lane] = __nv_bfloat162(lx, ly);
    }
}

// ================= mma.sync fused GEMM =================
#define SM_AHI  0
#define SM_ALO  16384
#define SM_BHI  32768
#define SM_BLO  49152
#define SM_RED  65536
#define SM_TOT  (65536 + 256)

__global__ void __launch_bounds__(256, 2) mma_gemm() {
    extern __shared__ char smem[];
    uint32_t sb = smem_u32(smem);
    int tid = threadIdx.x;
    int wid = tid >> 5;
    int lane = tid & 31;
    int warp_m = wid >> 2;
    int warp_n = wid & 3;
    int z = blockIdx.z;
    int b = z & 7;
    int job = z >> 3;
    int rowBase = blockIdx.y * 128;
    int colBase = blockIdx.x * 128;

    // ---- stage global -> smem ----
    const int TA[4] = {0, 0, 2, 4};
    const int TB[4] = {1, 3, 1, 5};
    {
        size_t aoff = ((size_t)TA[job] * 8192 + b * NP + rowBase) * ND;
        size_t boff = ((size_t)TB[job] * 8192 + b * NP + colBase) * ND;
        const uint4* sA = (const uint4*)(d_hi + aoff);
        const uint4* sB = (const uint4*)(d_hi + boff);
        #pragma unroll
        for (int it = 0; it < 4; it++) {
            int idx = it * 256 + tid;
            int r = idx >> 3, c = idx & 7;
            uint32_t so = sw128(r * 128 + c * 16);
            *(uint4*)(smem + SM_AHI + so) = sA[idx];
            *(uint4*)(smem + SM_BHI + so) = sB[idx];
        }
        if (job != 3) {
            const uint4* sAl = (const uint4*)(d_lo + aoff);
            const uint4* sBl = (const uint4*)(d_lo + boff);
            #pragma unroll
            for (int it = 0; it < 4; it++) {
                int idx = it * 256 + tid;
                int r = idx >> 3, c = idx & 7;
                uint32_t so = sw128(r * 128 + c * 16);
                *(uint4*)(smem + SM_ALO + so) = sAl[idx];
                *(uint4*)(smem + SM_BLO + so) = sBl[idx];
            }
        }
    }
    __syncthreads();

    // ---- mainloop: per k-step share A-hi frags for B-hi and B-lo, then A-lo * B-hi ----
    float acc[4][4][4];
    #pragma unroll
    for (int mi = 0; mi < 4; mi++)
        #pragma unroll
        for (int ni = 0; ni < 4; ni++)
            #pragma unroll
            for (int v = 0; v < 4; v++) acc[mi][ni][v] = 0.f;

    int mrow = warp_m * 64 + (lane & 15);
    int nrow = warp_n * 32 + (lane & 7);
    int l7 = lane & 7;

    #pragma unroll
    for (int k = 0; k < 4; k++) {
        uint32_t Af[4][4], Bh[4][2], Bl[4][2];
        int achunk = (2 * k + (lane >> 4)) ^ l7;
        int bchunk = (2 * k + ((lane >> 3) & 1)) ^ l7;
        #pragma unroll
        for (int mi = 0; mi < 4; mi++)
            ldsm_x4(Af[mi], sb + SM_AHI + (mrow + mi * 16) * 128 + achunk * 16);
        #pragma unroll
        for (int ni = 0; ni < 4; ni++)
            ldsm_x2(Bh[ni], sb + SM_BHI + (nrow + ni * 8) * 128 + bchunk * 16);
        #pragma unroll
        for (int mi = 0; mi < 4; mi++)
            #pragma unroll
            for (int ni = 0; ni < 4; ni++)
                mma_bf16(acc[mi][ni], Af[mi], Bh[ni]);           // hi*hi
        if (job != 3) {
            #pragma unroll
            for (int ni = 0; ni < 4; ni++)
                ldsm_x2(Bl[ni], sb + SM_BLO + (nrow + ni * 8) * 128 + bchunk * 16);
            #pragma unroll
            for (int mi = 0; mi < 4; mi++)
                #pragma unroll
                for (int ni = 0; ni < 4; ni++)
                    mma_bf16(acc[mi][ni], Af[mi], Bl[ni]);       // hi*lo
            #pragma unroll
            for (int mi = 0; mi < 4; mi++)
                ldsm_x4(Af[mi], sb + SM_ALO + (mrow + mi * 16) * 128 + achunk * 16);
            #pragma unroll
            for (int mi = 0; mi < 4; mi++)
                #pragma unroll
                for (int ni = 0; ni < 4; ni++)
                    mma_bf16(acc[mi][ni], Af[mi], Bh[ni]);       // lo*hi
        }
    }

    // ---- epilogue ----
    int g = lane >> 2, t4 = lane & 3;

    if (job == 3) {
        float h = 0.f;
        #pragma unroll
        for (int mi = 0; mi < 4; mi++)
            #pragma unroll
            for (int ni = 0; ni < 4; ni++)
                #pragma unroll
                for (int v = 0; v < 4; v++)
                    h += fmaxf(MARGIN - acc[mi][ni][v], 0.f);
        #pragma unroll
        for (int o = 16; o; o >>= 1) h += __shfl_xor_sync(0xFFFFFFFFu, h, o);
        float* red = (float*)(smem + SM_RED);
        if (lane == 0) red[wid] = h;
        __syncthreads();
        if (tid == 0) {
            float s = 0.f;
            #pragma unroll
            for (int w = 0; w < 8; w++) s += red[w];
            atomicAdd(&d_hinge, (double)s);
        }
        return;
    }

    float rs[4][2], cs[4][2];
    #pragma unroll
    for (int i = 0; i < 4; i++) { rs[i][0] = rs[i][1] = cs[i][0] = cs[i][1] = 0.f; }

    #pragma unroll
    for (int mi = 0; mi < 4; mi++) {
        int row = rowBase + warp_m * 64 + mi * 16 + g;
        #pragma unroll
        for (int ni = 0; ni < 4; ni++) {
            float e0 = __expf(GAMMA * acc[mi][ni][0]);
            float e1 = __expf(GAMMA * acc[mi][ni][1]);
            float e2 = __expf(GAMMA * acc[mi][ni][2]);
            float e3 = __expf(GAMMA * acc[mi][ni][3]);
            if (job == 0) {
                int col = colBase + warp_n * 32 + ni * 8 + t4 * 2;
                float* Cp = d_C + ((size_t)b * NP + row) * NP + col;
                *(float2*)Cp = make_float2(e0, e1);
                *(float2*)(Cp + (size_t)8 * NP) = make_float2(e2, e3);
            }
            rs[mi][0] += e0 + e1;  rs[mi][1] += e2 + e3;
            cs[ni][0] += e0 + e2;  cs[ni][1] += e1 + e3;
        }
    }

    if (job <= 1) {
        #pragma unroll
        for (int mi = 0; mi < 4; mi++) {
            float r0 = rs[mi][0], r1 = rs[mi][1];
            r0 += __shfl_xor_sync(0xFFFFFFFFu, r0, 1);
            r0 += __shfl_xor_sync(0xFFFFFFFFu, r0, 2);
            r1 += __shfl_xor_sync(0xFFFFFFFFu, r1, 1);
            r1 += __shfl_xor_sync(0xFFFFFFFFu, r1, 2);
            if (t4 == 0) {
                int row = rowBase + warp_m * 64 + mi * 16 + g;
                atomicAdd(&d_r[b * NP + row], r0);
                atomicAdd(&d_r[b * NP + row + 8], r1);
            }
        }
    }
    if (job == 0 || job == 2) {
        #pragma unroll
        for (int ni = 0; ni < 4; ni++) {
            float c0 = cs[ni][0], c1 = cs[ni][1];
            c0 += __shfl_xor_sync(0xFFFFFFFFu, c0, 4);
            c0 += __shfl_xor_sync(0xFFFFFFFFu, c0, 8);
            c0 += __shfl_xor_sync(0xFFFFFFFFu, c0, 16);
            c1 += __shfl_xor_sync(0xFFFFFFFFu, c1, 4);
            c1 += __shfl_xor_sync(0xFFFFFFFFu, c1, 8);
            c1 += __shfl_xor_sync(0xFFFFFFFFu, c1, 16);
            if (lane < 4) {
                int col = colBase + warp_n * 32 + ni * 8 + lane * 2;
                atomicAdd(&d_c[b * NP + col], c0);
                atomicAdd(&d_c[b * NP + col + 1], c1);
            }
        }
    }
}

// ================= finalize: C = 1 - S/(r+c-S) -> u16 Cq + u16 CTq =================
__global__ void finalize_kernel() {
    __shared__ float tile[64][68];
    int b = blockIdx.z;
    int pBase = blockIdx.y * 64, qBase = blockIdx.x * 64;
    int tid = threadIdx.x;  // 256
    #pragma unroll
    for (int v = 0; v < 4; v++) {
        int f4 = v * 256 + tid;
        int row = f4 >> 4;
        int c4 = f4 & 15;
        int p = pBase + row;
        size_t idx = ((size_t)b * NP + p) * NP + qBase + c4 * 4;
        float4 S = *(const float4*)(d_C + idx);
        float rp = d_r[b * NP + p];
        float4 cq = *(const float4*)(d_c + b * NP + qBase + c4 * 4);
        float4 C;
        C.x = 1.f - __fdividef(S.x, rp + cq.x - S.x);
        C.y = 1.f - __fdividef(S.y, rp + cq.y - S.y);
        C.z = 1.f - __fdividef(S.z, rp + cq.z - S.z);
        C.w = 1.f - __fdividef(S.w, rp + cq.w - S.w);
        ushort4 q = make_ushort4(quant(C.x), quant(C.y), quant(C.z), quant(C.w));
        *(ushort4*)(d_Cq + idx) = q;
        *(float4*)&tile[row][c4 * 4] = C;
    }
    __syncthreads();
    #pragma unroll
    for (int v = 0; v < 4; v++) {
        int f4 = v * 256 + tid;
        int qr = f4 >> 4;
        int p4 = f4 & 15;
        ushort4 o;
        o.x = quant(tile[p4 * 4 + 0][qr]);
        o.y = quant(tile[p4 * 4 + 1][qr]);
        o.z = quant(tile[p4 * 4 + 2][qr]);
        o.w = quant(tile[p4 * 4 + 3][qr]);
        *(ushort4*)(d_CTq + ((size_t)b * NP + qBase + qr) * NP + pBase + p4 * 4) = o;
    }
}

// ================= fused softmin: block = one (side,b) slice, h cached in smem =================
__global__ void softmin_kernel(int src, int dst, float eps, int mode) {
    __shared__ float hs[NP];
    __shared__ double blkred[8];
    int bx = blockIdx.x;          // 2048 blocks
    int slice = bx >> 7;          // side*8 + b
    int side = slice >> 3;
    int b = slice & 7;
    int rowgrp = bx & 127;
    int tid = threadIdx.x;
    int wid = tid >> 5, lane = tid & 31;

    // load opposite dual (or zeros) into smem once per block
    if (mode == 0) {
        for (int i = tid; i < NP; i += 256) hs[i] = 0.f;
    } else {
        const float* hsrc = (side == 0 ? d_g[src] : d_f[src]) + b * NP;
        for (int i = tid; i < NP; i += 256) hs[i] = hsrc[i];
    }
    __syncthreads();

    int row = rowgrp * 8 + wid;
    int idx = b * NP + row;
    const uint4* rowp = (const uint4*)((side == 0 ? d_Cq : d_CTq) + (size_t)idx * NP);
    const float4* h4 = (const float4*)hs;

    float u[32];
    float m = -3.4e38f;
    #pragma unroll
    for (int j = 0; j < 4; j++) {
        uint4 q = rowp[j * 32 + lane];
        float4 h0 = h4[(j * 32 + lane) * 2];
        float4 h1 = h4[(j * 32 + lane) * 2 + 1];
        float* uu = u + j * 8;
        uu[0] = h0.x - (float)(q.x & 0xFFFF) * IQSCALE;
        uu[1] = h0.y - (float)(q.x >> 16) * IQSCALE;
        uu[2] = h0.z - (float)(q.y & 0xFFFF) * IQSCALE;
        uu[3] = h0.w - (float)(q.y >> 16) * IQSCALE;
        uu[4] = h1.x - (float)(q.z & 0xFFFF) * IQSCALE;
        uu[5] = h1.y - (float)(q.z >> 16) * IQSCALE;
        uu[6] = h1.z - (float)(q.w & 0xFFFF) * IQSCALE;
        uu[7] = h1.w - (float)(q.w >> 16) * IQSCALE;
        #pragma unroll
        for (int i = 0; i < 8; i++) m = fmaxf(m, uu[i]);
    }
    #pragma unroll
    for (int o = 16; o; o >>= 1) m = fmaxf(m, __shfl_xor_sync(0xFFFFFFFFu, m, o));

    float k2 = 1.4426950408889634f / eps;   // log2(e)/eps
    float s0 = 0, s1 = 0, s2 = 0, s3 = 0;
    #pragma unroll
    for (int i = 0; i < 8; i++) {
        s0 += exp2f((u[4 * i + 0] - m) * k2);
        s1 += exp2f((u[4 * i + 1] - m) * k2);
        s2 += exp2f((u[4 * i + 2] - m) * k2);
        s3 += exp2f((u[4 * i + 3] - m) * k2);
    }
    float sum = (s0 + s1) + (s2 + s3);
    #pragma unroll
    for (int o = 16; o; o >>= 1) sum += __shfl_xor_sync(0xFFFFFFFFu, sum, o);

    if (mode == 2) {
        if (lane == 0) {
            float val = -(m + eps * 0.69314718055994531f * __log2f(sum));
            blkred[wid] = (double)val;
        }
        __syncthreads();
        if (tid == 0) {
            double t = ((blkred[0] + blkred[1]) + (blkred[2] + blkred[3]))
                     + ((blkred[4] + blkred[5]) + (blkred[6] + blkred[7]));
            atomicAdd(&d_scon, t);
        }
    } else if (lane == 0) {
        float val = -(m + eps * 0.69314718055994531f * __log2f(sum));
        if (mode == 1) {
            float prev = (side == 0 ? d_f[src] : d_g[src])[idx];
            val = 0.5f * (prev + val);
        }
        (side == 0 ? d_f[dst] : d_g[dst])[idx] = val;
    }
}

// ================= output =================
__global__ void write_out(float* out) {
    if (threadIdx.x == 0) {
        out[0] = (float)d_hinge;
        out[1] = (float)(d_scon / 8.0);
    }
}

// ================= launch =================
extern "C" void kernel_launch(void* const* d_in, const int* in_sizes, int n_in,
                              void* d_out, int out_size) {
    (void)in_sizes; (void)n_in; (void)out_size;
    const float* x1 = (const float*)d_in[0];
    const float* x2 = (const float*)d_in[1];
    const float* x3 = (const float*)d_in[2];
    const float* x4 = (const float*)d_in[3];
    float* out = (float*)d_out;

    double pexp = 2.0, diam = 3.0, blur = 0.05, scal = 0.5;
    float eps_list[16];
    int n_eps = 0;
    eps_list[n_eps++] = (float)pow(diam, pexp);
    for (double v = pexp * log(diam); v > pexp * log(blur); v += pexp * log(scal))
        eps_list[n_eps++] = (float)exp(v);
    eps_list[n_eps++] = (float)pow(blur, pexp);   // n_eps == 8

    cudaFuncSetAttribute(mma_gemm, cudaFuncAttributeMaxDynamicSharedMemorySize, SM_TOT);

    reset_kernel<<<32, 256>>>();
    norm_split<<<6144, 256>>>(x1, x2, x3, x4);

    mma_gemm<<<dim3(8, 8, 32), 256, SM_TOT>>>();

    finalize_kernel<<<dim3(16, 16, NB), 256>>>();

    softmin_kernel<<<2048, 256>>>(0, 0, eps_list[0], 0);
    int cur = 0;
    for (int i = 0; i < n_eps; i++) {
        softmin_kernel<<<2048, 256>>>(cur, 1 - cur, eps_list[i], 1);
        cur = 1 - cur;
    }
    softmin_kernel<<<2048, 256>>>(cur, cur, eps_list[n_eps - 1], 2);

    write_out<<<1, 1>>>(out);
}

// round 8
// speedup vs baseline: 1.9310x; 1.0087x over previous
#include <cuda_runtime.h>
#include <cuda_bf16.h>
#include <math.h>
#include <stdint.h>

#define NB 8
#define NP 1024
#define ND 64
#define GAMMA 10.0f
#define MARGIN 0.1f
#define QSCALE 65535.0f
#define IQSCALE (1.0f / 65535.0f)

// ================= device scratch =================
__device__ __nv_bfloat16 d_hi[6 * NB * NP * ND];
__device__ __nv_bfloat16 d_lo[6 * NB * NP * ND];
__device__ float d_C[NB * NP * NP];                  // sim S (32 MB), dead after finalize
__device__ unsigned short d_Cq[NB * NP * NP];        // u16 cost (16 MB)
__device__ unsigned short d_CTq[NB * NP * NP];       // u16 transposed cost (16 MB)
__device__ float d_r[NB * NP];
__device__ float d_c[NB * NP];
__device__ float d_fs[NB * NP];                      // init row sums  e^{-C/9}
__device__ float d_gs[NB * NP];                      // init col sums  e^{-C/9}
__device__ float d_f[2][NB * NP];
__device__ float d_g[2][NB * NP];
__device__ double d_hinge;
__device__ double d_scon;

// ================= helpers =================
__device__ __forceinline__ uint32_t smem_u32(const void* p) {
    uint32_t a;
    asm("{ .reg .u64 t; cvta.to.shared.u64 t, %1; cvt.u32.u64 %0, t; }" : "=r"(a) : "l"(p));
    return a;
}
__device__ __forceinline__ uint32_t sw128(uint32_t off) { return off ^ ((off >> 3) & 0x70); }

__device__ __forceinline__ void ldsm_x4(uint32_t* r, uint32_t addr) {
    asm volatile("ldmatrix.sync.aligned.m8n8.x4.shared.b16 {%0,%1,%2,%3}, [%4];"
        : "=r"(r[0]), "=r"(r[1]), "=r"(r[2]), "=r"(r[3]) : "r"(addr));
}
__device__ __forceinline__ void ldsm_x2(uint32_t* r, uint32_t addr) {
    asm volatile("ldmatrix.sync.aligned.m8n8.x2.shared.b16 {%0,%1}, [%2];"
        : "=r"(r[0]), "=r"(r[1]) : "r"(addr));
}
__device__ __forceinline__ void mma_bf16(float* d, const uint32_t* a, const uint32_t* b) {
    asm volatile("mma.sync.aligned.m16n8k16.row.col.f32.bf16.bf16.f32 "
        "{%0,%1,%2,%3}, {%4,%5,%6,%7}, {%8,%9}, {%0,%1,%2,%3};"
        : "+f"(d[0]), "+f"(d[1]), "+f"(d[2]), "+f"(d[3])
        : "r"(a[0]), "r"(a[1]), "r"(a[2]), "r"(a[3]), "r"(b[0]), "r"(b[1]));
}
__device__ __forceinline__ unsigned short quant(float v) {
    return (unsigned short)__float2uint_rn(fminf(fmaxf(v, 0.f), 1.f) * QSCALE);
}

// ================= reset =================
__global__ void reset_kernel() {
    int i = blockIdx.x * blockDim.x + threadIdx.x;
    if (i < NB * NP) { d_r[i] = 0.f; d_c[i] = 0.f; d_fs[i] = 0.f; d_gs[i] = 0.f; }
    if (i == 0) { d_hinge = 0.0; d_scon = 0.0; }
}

// ================= normalize + hi/lo split =================
__global__ void norm_split(const float* __restrict__ x1, const float* __restrict__ x2,
                           const float* __restrict__ x3, const float* __restrict__ x4) {
    int w = (blockIdx.x * blockDim.x + threadIdx.x) >> 5;
    int lane = threadIdx.x & 31;
    int t = w / 8192;
    int row = w - t * 8192;
    const float* src = (t == 0) ? x1 : (t == 1) ? x2 : (t == 2 || t == 4) ? x3 : x4;
    float2 v = ((const float2*)(src + (size_t)row * ND))[lane];
    if (t < 4) {
        float ss = v.x * v.x + v.y * v.y;
        #pragma unroll
        for (int o = 16; o; o >>= 1) ss += __shfl_xor_sync(0xFFFFFFFFu, ss, o);
        float sc = 1.0f / fmaxf(sqrtf(ss), 1e-12f);
        v.x *= sc; v.y *= sc;
    }
    __nv_bfloat16 hx = __float2bfloat16(v.x);
    __nv_bfloat16 hy = __float2bfloat16(v.y);
    size_t base = ((size_t)t * 8192 + row) * ND;
    ((__nv_bfloat162*)(d_hi + base))[lane] = __nv_bfloat162(hx, hy);
    if (t < 4) {
        __nv_bfloat16 lx = __float2bfloat16(v.x - __bfloat162float(hx));
        __nv_bfloat16 ly = __float2bfloat16(v.y - __bfloat162float(hy));
        ((__nv_bfloat162*)(d_lo + base))[lane] = __nv_bfloat162(lx, ly);
    }
}

// ================= mma.sync fused GEMM (unchanged from R7) =================
#define SM_AHI  0
#define SM_ALO  16384
#define SM_BHI  32768
#define SM_BLO  49152
#define SM_RED  65536
#define SM_TOT  (65536 + 256)

__global__ void __launch_bounds__(256, 2) mma_gemm() {
    extern __shared__ char smem[];
    uint32_t sb = smem_u32(smem);
    int tid = threadIdx.x;
    int wid = tid >> 5;
    int lane = tid & 31;
    int warp_m = wid >> 2;
    int warp_n = wid & 3;
    int z = blockIdx.z;
    int b = z & 7;
    int job = z >> 3;
    int rowBase = blockIdx.y * 128;
    int colBase = blockIdx.x * 128;

    const int TA[4] = {0, 0, 2, 4};
    const int TB[4] = {1, 3, 1, 5};
    {
        size_t aoff = ((size_t)TA[job] * 8192 + b * NP + rowBase) * ND;
        size_t boff = ((size_t)TB[job] * 8192 + b * NP + colBase) * ND;
        const uint4* sA = (const uint4*)(d_hi + aoff);
        const uint4* sB = (const uint4*)(d_hi + boff);
        #pragma unroll
        for (int it = 0; it < 4; it++) {
            int idx = it * 256 + tid;
            int r = idx >> 3, c = idx & 7;
            uint32_t so = sw128(r * 128 + c * 16);
            *(uint4*)(smem + SM_AHI + so) = sA[idx];
            *(uint4*)(smem + SM_BHI + so) = sB[idx];
        }
        if (job != 3) {
            const uint4* sAl = (const uint4*)(d_lo + aoff);
            const uint4* sBl = (const uint4*)(d_lo + boff);
            #pragma unroll
            for (int it = 0; it < 4; it++) {
                int idx = it * 256 + tid;
                int r = idx >> 3, c = idx & 7;
                uint32_t so = sw128(r * 128 + c * 16);
                *(uint4*)(smem + SM_ALO + so) = sAl[idx];
                *(uint4*)(smem + SM_BLO + so) = sBl[idx];
            }
        }
    }
    __syncthreads();

    float acc[4][4][4];
    #pragma unroll
    for (int mi = 0; mi < 4; mi++)
        #pragma unroll
        for (int ni = 0; ni < 4; ni++)
            #pragma unroll
            for (int v = 0; v < 4; v++) acc[mi][ni][v] = 0.f;

    int mrow = warp_m * 64 + (lane & 15);
    int nrow = warp_n * 32 + (lane & 7);
    int l7 = lane & 7;

    #pragma unroll
    for (int k = 0; k < 4; k++) {
        uint32_t Af[4][4], Bh[4][2], Bl[4][2];
        int achunk = (2 * k + (lane >> 4)) ^ l7;
        int bchunk = (2 * k + ((lane >> 3) & 1)) ^ l7;
        #pragma unroll
        for (int mi = 0; mi < 4; mi++)
            ldsm_x4(Af[mi], sb + SM_AHI + (mrow + mi * 16) * 128 + achunk * 16);
        #pragma unroll
        for (int ni = 0; ni < 4; ni++)
            ldsm_x2(Bh[ni], sb + SM_BHI + (nrow + ni * 8) * 128 + bchunk * 16);
        #pragma unroll
        for (int mi = 0; mi < 4; mi++)
            #pragma unroll
            for (int ni = 0; ni < 4; ni++)
                mma_bf16(acc[mi][ni], Af[mi], Bh[ni]);           // hi*hi
        if (job != 3) {
            #pragma unroll
            for (int ni = 0; ni < 4; ni++)
                ldsm_x2(Bl[ni], sb + SM_BLO + (nrow + ni * 8) * 128 + bchunk * 16);
            #pragma unroll
            for (int mi = 0; mi < 4; mi++)
                #pragma unroll
                for (int ni = 0; ni < 4; ni++)
                    mma_bf16(acc[mi][ni], Af[mi], Bl[ni]);       // hi*lo
            #pragma unroll
            for (int mi = 0; mi < 4; mi++)
                ldsm_x4(Af[mi], sb + SM_ALO + (mrow + mi * 16) * 128 + achunk * 16);
            #pragma unroll
            for (int mi = 0; mi < 4; mi++)
                #pragma unroll
                for (int ni = 0; ni < 4; ni++)
                    mma_bf16(acc[mi][ni], Af[mi], Bh[ni]);       // lo*hi
        }
    }

    int g = lane >> 2, t4 = lane & 3;

    if (job == 3) {
        float h = 0.f;
        #pragma unroll
        for (int mi = 0; mi < 4; mi++)
            #pragma unroll
            for (int ni = 0; ni < 4; ni++)
                #pragma unroll
                for (int v = 0; v < 4; v++)
                    h += fmaxf(MARGIN - acc[mi][ni][v], 0.f);
        #pragma unroll
        for (int o = 16; o; o >>= 1) h += __shfl_xor_sync(0xFFFFFFFFu, h, o);
        float* red = (float*)(smem + SM_RED);
        if (lane == 0) red[wid] = h;
        __syncthreads();
        if (tid == 0) {
            float s = 0.f;
            #pragma unroll
            for (int w = 0; w < 8; w++) s += red[w];
            atomicAdd(&d_hinge, (double)s);
        }
        return;
    }

    float rs[4][2], cs[4][2];
    #pragma unroll
    for (int i = 0; i < 4; i++) { rs[i][0] = rs[i][1] = cs[i][0] = cs[i][1] = 0.f; }

    #pragma unroll
    for (int mi = 0; mi < 4; mi++) {
        int row = rowBase + warp_m * 64 + mi * 16 + g;
        #pragma unroll
        for (int ni = 0; ni < 4; ni++) {
            float e0 = __expf(GAMMA * acc[mi][ni][0]);
            float e1 = __expf(GAMMA * acc[mi][ni][1]);
            float e2 = __expf(GAMMA * acc[mi][ni][2]);
            float e3 = __expf(GAMMA * acc[mi][ni][3]);
            if (job == 0) {
                int col = colBase + warp_n * 32 + ni * 8 + t4 * 2;
                float* Cp = d_C + ((size_t)b * NP + row) * NP + col;
                *(float2*)Cp = make_float2(e0, e1);
                *(float2*)(Cp + (size_t)8 * NP) = make_float2(e2, e3);
            }
            rs[mi][0] += e0 + e1;  rs[mi][1] += e2 + e3;
            cs[ni][0] += e0 + e2;  cs[ni][1] += e1 + e3;
        }
    }

    if (job <= 1) {
        #pragma unroll
        for (int mi = 0; mi < 4; mi++) {
            float r0 = rs[mi][0], r1 = rs[mi][1];
            r0 += __shfl_xor_sync(0xFFFFFFFFu, r0, 1);
            r0 += __shfl_xor_sync(0xFFFFFFFFu, r0, 2);
            r1 += __shfl_xor_sync(0xFFFFFFFFu, r1, 1);
            r1 += __shfl_xor_sync(0xFFFFFFFFu, r1, 2);
            if (t4 == 0) {
                int row = rowBase + warp_m * 64 + mi * 16 + g;
                atomicAdd(&d_r[b * NP + row], r0);
                atomicAdd(&d_r[b * NP + row + 8], r1);
            }
        }
    }
    if (job == 0 || job == 2) {
        #pragma unroll
        for (int ni = 0; ni < 4; ni++) {
            float c0 = cs[ni][0], c1 = cs[ni][1];
            c0 += __shfl_xor_sync(0xFFFFFFFFu, c0, 4);
            c0 += __shfl_xor_sync(0xFFFFFFFFu, c0, 8);
            c0 += __shfl_xor_sync(0xFFFFFFFFu, c0, 16);
            c1 += __shfl_xor_sync(0xFFFFFFFFu, c1, 4);
            c1 += __shfl_xor_sync(0xFFFFFFFFu, c1, 8);
            c1 += __shfl_xor_sync(0xFFFFFFFFu, c1, 16);
            if (lane < 4) {
                int col = colBase + warp_n * 32 + ni * 8 + lane * 2;
                atomicAdd(&d_c[b * NP + col], c0);
                atomicAdd(&d_c[b * NP + col + 1], c1);
            }
        }
    }
}

// ================= finalize: C -> u16 Cq/CTq + fused init-softmin sums =================
// accumulates d_fs[row] += sum_col e^{-C/9}, d_gs[col] += sum_row e^{-C/9}
__global__ void finalize_kernel() {
    __shared__ float tile[64][68];
    __shared__ float scol[64];
    int b = blockIdx.z;
    int pBase = blockIdx.y * 64, qBase = blockIdx.x * 64;
    int tid = threadIdx.x;  // 256
    int lane = tid & 31;
    const float NK9 = -0.16029948f;   // -log2(e)/9
    float cpart[4] = {0.f, 0.f, 0.f, 0.f};
    float rpart[4];
    if (tid < 64) scol[tid] = 0.f;
    __syncthreads();
    #pragma unroll
    for (int v = 0; v < 4; v++) {
        int f4 = v * 256 + tid;
        int row = f4 >> 4;
        int c4 = f4 & 15;
        int p = pBase + row;
        size_t idx = ((size_t)b * NP + p) * NP + qBase + c4 * 4;
        float4 S = *(const float4*)(d_C + idx);
        float rp = d_r[b * NP + p];
        float4 cq = *(const float4*)(d_c + b * NP + qBase + c4 * 4);
        float4 C;
        C.x = 1.f - __fdividef(S.x, rp + cq.x - S.x);
        C.y = 1.f - __fdividef(S.y, rp + cq.y - S.y);
        C.z = 1.f - __fdividef(S.z, rp + cq.z - S.z);
        C.w = 1.f - __fdividef(S.w, rp + cq.w - S.w);
        ushort4 q = make_ushort4(quant(C.x), quant(C.y), quant(C.z), quant(C.w));
        *(ushort4*)(d_Cq + idx) = q;
        *(float4*)&tile[row][c4 * 4] = C;
        float e0 = exp2f(C.x * NK9);
        float e1 = exp2f(C.y * NK9);
        float e2 = exp2f(C.z * NK9);
        float e3 = exp2f(C.w * NK9);
        rpart[v] = (e0 + e1) + (e2 + e3);
        cpart[0] += e0; cpart[1] += e1; cpart[2] += e2; cpart[3] += e3;
    }
    // row sums: lanes 0-15 / 16-31 each share one row per v
    #pragma unroll
    for (int v = 0; v < 4; v++) {
        float r = rpart[v];
        r += __shfl_xor_sync(0xFFFFFFFFu, r, 1);
        r += __shfl_xor_sync(0xFFFFFFFFu, r, 2);
        r += __shfl_xor_sync(0xFFFFFFFFu, r, 4);
        r += __shfl_xor_sync(0xFFFFFFFFu, r, 8);
        if ((lane & 15) == 0)
            atomicAdd(&d_fs[b * NP + pBase + v * 16 + (tid >> 4)], r);
    }
    // col sums: combine lane pairs (l, l+16) then smem, then global
    #pragma unroll
    for (int j = 0; j < 4; j++) {
        cpart[j] += __shfl_xor_sync(0xFFFFFFFFu, cpart[j], 16);
        if (lane < 16) atomicAdd(&scol[lane * 4 + j], cpart[j]);
    }
    __syncthreads();
    if (tid < 64) atomicAdd(&d_gs[b * NP + qBase + tid], scol[tid]);

    // transpose -> CTq
    #pragma unroll
    for (int v = 0; v < 4; v++) {
        int f4 = v * 256 + tid;
        int qr = f4 >> 4;
        int p4 = f4 & 15;
        ushort4 o;
        o.x = quant(tile[p4 * 4 + 0][qr]);
        o.y = quant(tile[p4 * 4 + 1][qr]);
        o.z = quant(tile[p4 * 4 + 2][qr]);
        o.w = quant(tile[p4 * 4 + 3][qr]);
        *(ushort4*)(d_CTq + ((size_t)b * NP + qBase + qr) * NP + pBase + p4 * 4) = o;
    }
}

// ================= fused softmin =================
// mode 1: loop update (averaged), mode 2: final accumulate into d_scon
// init: read duals from init sums via -9*ln(.)
// use_max: subtract per-row max (needed only for small eps)
__global__ void softmin_kernel(int src, int dst, float eps, int mode, int init, int use_max) {
    __shared__ float hs[NP];
    __shared__ double blkred[8];
    int bx = blockIdx.x;
    int slice = bx >> 7;
    int side = slice >> 3;
    int b = slice & 7;
    int rowgrp = bx & 127;
    int tid = threadIdx.x;
    int wid = tid >> 5, lane = tid & 31;

    float k2 = 1.4426950408889634f / eps;
    const float* hsrc = (side == 0 ? (init ? d_gs : d_g[src]) : (init ? d_fs : d_f[src])) + b * NP;
    for (int i = tid; i < NP; i += 256) {
        float h = hsrc[i];
        if (init) h = -9.0f * __logf(h);
        hs[i] = h * k2;
    }
    __syncthreads();

    int row = rowgrp * 8 + wid;
    int idx = b * NP + row;
    const uint4* rowp = (const uint4*)((side == 0 ? d_Cq : d_CTq) + (size_t)idx * NP);
    const float4* h4 = (const float4*)hs;
    float qk = -IQSCALE * k2;

    float t[32];
    #pragma unroll
    for (int j = 0; j < 4; j++) {
        uint4 q = rowp[j * 32 + lane];
        float4 h0 = h4[(j * 32 + lane) * 2];
        float4 h1 = h4[(j * 32 + lane) * 2 + 1];
        float* tt = t + j * 8;
        tt[0] = fmaf((float)(q.x & 0xFFFF), qk, h0.x);
        tt[1] = fmaf((float)(q.x >> 16),    qk, h0.y);
        tt[2] = fmaf((float)(q.y & 0xFFFF), qk, h0.z);
        tt[3] = fmaf((float)(q.y >> 16),    qk, h0.w);
        tt[4] = fmaf((float)(q.z & 0xFFFF), qk, h1.x);
        tt[5] = fmaf((float)(q.z >> 16),    qk, h1.y);
        tt[6] = fmaf((float)(q.w & 0xFFFF), qk, h1.z);
        tt[7] = fmaf((float)(q.w >> 16),    qk, h1.w);
    }

    float m = 0.f;
    if (use_max) {
        m = t[0];
        #pragma unroll
        for (int i = 1; i < 32; i++) m = fmaxf(m, t[i]);
        #pragma unroll
        for (int o = 16; o; o >>= 1) m = fmaxf(m, __shfl_xor_sync(0xFFFFFFFFu, m, o));
    }

    float s0 = 0, s1 = 0, s2 = 0, s3 = 0;
    #pragma unroll
    for (int i = 0; i < 8; i++) {
        s0 += exp2f(t[4 * i + 0] - m);
        s1 += exp2f(t[4 * i + 1] - m);
        s2 += exp2f(t[4 * i + 2] - m);
        s3 += exp2f(t[4 * i + 3] - m);
    }
    float sum = (s0 + s1) + (s2 + s3);
    #pragma unroll
    for (int o = 16; o; o >>= 1) sum += __shfl_xor_sync(0xFFFFFFFFu, sum, o);

    const float ELN2 = 0.69314718055994531f;
    if (mode == 2) {
        if (lane == 0) {
            float val = -eps * ELN2 * (m + __log2f(sum));
            blkred[wid] = (double)val;
        }
        __syncthreads();
        if (tid == 0) {
            double tacc = ((blkred[0] + blkred[1]) + (blkred[2] + blkred[3]))
                        + ((blkred[4] + blkred[5]) + (blkred[6] + blkred[7]));
            atomicAdd(&d_scon, tacc);
        }
    } else if (lane == 0) {
        float val = -eps * ELN2 * (m + __log2f(sum));
        float prev;
        if (init) prev = -9.0f * __logf((side == 0 ? d_fs : d_gs)[idx]);
        else prev = (side == 0 ? d_f[src] : d_g[src])[idx];
        val = 0.5f * (prev + val);
        (side == 0 ? d_f[dst] : d_g[dst])[idx] = val;
    }
}

// ================= output =================
__global__ void write_out(float* out) {
    if (threadIdx.x == 0) {
        out[0] = (float)d_hinge;
        out[1] = (float)(d_scon / 8.0);
    }
}

// ================= launch =================
extern "C" void kernel_launch(void* const* d_in, const int* in_sizes, int n_in,
                              void* d_out, int out_size) {
    (void)in_sizes; (void)n_in; (void)out_size;
    const float* x1 = (const float*)d_in[0];
    const float* x2 = (const float*)d_in[1];
    const float* x3 = (const float*)d_in[2];
    const float* x4 = (const float*)d_in[3];
    float* out = (float*)d_out;

    double pexp = 2.0, diam = 3.0, blur = 0.05, scal = 0.5;
    float eps_list[16];
    int n_eps = 0;
    eps_list[n_eps++] = (float)pow(diam, pexp);
    for (double v = pexp * log(diam); v > pexp * log(blur); v += pexp * log(scal))
        eps_list[n_eps++] = (float)exp(v);
    eps_list[n_eps++] = (float)pow(blur, pexp);   // n_eps == 8

    cudaFuncSetAttribute(mma_gemm, cudaFuncAttributeMaxDynamicSharedMemorySize, SM_TOT);

    reset_kernel<<<32, 256>>>();
    norm_split<<<6144, 256>>>(x1, x2, x3, x4);

    mma_gemm<<<dim3(8, 8, 32), 256, SM_TOT>>>();

    finalize_kernel<<<dim3(16, 16, NB), 256>>>();   // also produces init sums

    int cur = 0;
    for (int i = 0; i < n_eps; i++) {
        int init = (i == 0) ? 1 : 0;
        int use_max = (eps_list[i] < 0.02f) ? 1 : 0;
        softmin_kernel<<<2048, 256>>>(cur, 1 - cur, eps_list[i], 1, init, use_max);
        cur = 1 - cur;
    }
    softmin_kernel<<<2048, 256>>>(cur, cur, eps_list[n_eps - 1], 2, 0, 1);

    write_out<<<1, 1>>>(out);
}